// round 3
// baseline (speedup 1.0000x reference)
#include <cuda_runtime.h>
#include <cuda_bf16.h>
#include <cstdint>
#include <math.h>

// ============================================================================
// Problem constants
//   x1,x2: [32,1024,768]  -> stacked X: [65536, 768]
//   P = X @ [Wq | Wk | Wv | W1a | W1b]  : [65536, 2688]
//   bf16 3-term split folded into K: A' = [Xhi | Xlo | Xhi] (K=2304),
//   B' = [Whi ; Whi ; Wlo].  Physical storage is [hi|lo] (1536) + k remap.
// ============================================================================
#define MTOT   65536
#define DIM    768
#define NPAD   2688            // 21 * 128, exact
#define KPHYS  1536
#define KEFF   2304

#define BM 128
#define BN 128
#define BK 64
#define KT (KEFF / BK)         // 36
#define STAGES 3

// ============================================================================
// Scratch (__device__ globals)
// ============================================================================
__device__ __nv_bfloat16 g_Xc[(long)MTOT * KPHYS];   // [65536][1536] bf16 (hi|lo)
__device__ __nv_bfloat16 g_Wc[(long)NPAD * KPHYS];   // [2688][1536]  bf16 (hi|lo), n-major
__device__ float         g_P [(long)MTOT * NPAD];    // [65536][2688] fp32
__device__ float         g_nk[DIM];                  // noise @ Wk

// ============================================================================
// Helpers
// ============================================================================
__device__ __forceinline__ uint32_t smem_to_u32(const void* smem_ptr) {
    uint32_t addr;
    asm("{ .reg .u64 tmp; cvta.to.shared.u64 tmp, %1; cvt.u32.u64 %0, tmp; }"
        : "=r"(addr) : "l"(smem_ptr));
    return addr;
}

#define SWZ(byte_offset) ((byte_offset) ^ ((((uint32_t)(byte_offset)) >> 3) & 0x70))

__device__ __forceinline__ void cp_async16(uint32_t dst_smem, const void* src) {
    asm volatile("cp.async.cg.shared.global [%0], [%1], 16;"
        :: "r"(dst_smem), "l"(src) : "memory");
}
#define CP_ASYNC_COMMIT()  asm volatile("cp.async.commit_group;" ::: "memory")
#define CP_ASYNC_WAIT(N)   asm volatile("cp.async.wait_group %0;" :: "n"(N) : "memory")

__device__ __forceinline__ void ldsm_x4(uint32_t* r, uint32_t addr) {
    asm volatile("ldmatrix.sync.aligned.m8n8.x4.shared.b16 {%0,%1,%2,%3}, [%4];"
        : "=r"(r[0]), "=r"(r[1]), "=r"(r[2]), "=r"(r[3]) : "r"(addr));
}

__device__ __forceinline__ void mma16816(float* c, const uint32_t* a, const uint32_t* b) {
    asm volatile(
        "mma.sync.aligned.m16n8k16.row.col.f32.bf16.bf16.f32 "
        "{%0,%1,%2,%3}, {%4,%5,%6,%7}, {%8,%9}, {%0,%1,%2,%3};"
        : "+f"(c[0]), "+f"(c[1]), "+f"(c[2]), "+f"(c[3])
        : "r"(a[0]), "r"(a[1]), "r"(a[2]), "r"(a[3]), "r"(b[0]), "r"(b[1]));
}

// ============================================================================
// Prep kernels
// ============================================================================
__global__ void prep_x_kernel(const float* __restrict__ x1,
                              const float* __restrict__ x2) {
    long r = blockIdx.x;
    const float* src = (r < (MTOT / 2)) ? (x1 + r * DIM)
                                        : (x2 + (r - MTOT / 2) * DIM);
    __nv_bfloat16* dst = g_Xc + r * KPHYS;
    for (int c = threadIdx.x; c < DIM; c += blockDim.x) {
        float v = src[c];
        __nv_bfloat16 hi = __float2bfloat16(v);
        float lo = v - __bfloat162float(hi);
        dst[c] = hi;
        dst[DIM + c] = __float2bfloat16(lo);
    }
}

__global__ void prep_w_kernel(const float* __restrict__ Wq,
                              const float* __restrict__ Wk,
                              const float* __restrict__ Wv,
                              const float* __restrict__ W1) {
    int n = blockIdx.x;  // 0..NPAD-1 (NPAD == logical 2688, no pad)
    __nv_bfloat16* dst = g_Wc + (long)n * KPHYS;
    for (int j = threadIdx.x; j < DIM; j += blockDim.x) {
        float w;
        if      (n < 768)  w = Wq[j * 768 + n];
        else if (n < 1536) w = Wk[j * 768 + (n - 768)];
        else if (n < 2304) w = Wv[j * 768 + (n - 1536)];
        else if (n < 2496) w = W1[j * 192 + (n - 2304)];          // W1a (rows 0..767)
        else               w = W1[(768 + j) * 192 + (n - 2496)];  // W1b (rows 768..1535)
        __nv_bfloat16 hi = __float2bfloat16(w);
        dst[j] = hi;
        dst[DIM + j] = __float2bfloat16(w - __bfloat162float(hi));
    }
}

__global__ void nk_kernel(const float* __restrict__ noise,
                          const float* __restrict__ Wk) {
    int d = blockIdx.x * blockDim.x + threadIdx.x;
    if (d >= DIM) return;
    float acc = 0.0f;
    for (int j = 0; j < DIM; j++) acc += noise[j] * Wk[j * 768 + d];
    g_nk[d] = acc;
}

// ============================================================================
// GEMM: P[65536, 2688] = A'[65536, 2304] @ B'[2688, 2304]^T  (bf16 -> fp32)
// mma.sync.m16n8k16 path (compute_103-safe). 256 threads, 8 warps (4 m x 2 n).
// smem: STAGES x (A 16KB + B 16KB), SW128 swizzle, cp.async 3-stage pipeline.
// ============================================================================
#define STAGE_BYTES 32768
#define SM_TOTAL    (STAGES * STAGE_BYTES)

__global__ void __launch_bounds__(256, 2) gemm_kernel() {
    extern __shared__ char smem[];
    const uint32_t sbase = smem_to_u32(smem);
    const int tid    = threadIdx.x;
    const int wid    = tid >> 5;
    const int lane   = tid & 31;
    const int warp_m = wid & 3;   // 0..3, 32 rows each
    const int warp_n = wid >> 2;  // 0..1, 64 cols each
    const int m0 = blockIdx.y * BM;
    const int n0 = blockIdx.x * BN;

    const __nv_bfloat16* Ag = g_Xc + (long)m0 * KPHYS;
    const __nv_bfloat16* Bg = g_Wc + (long)n0 * KPHYS;

    auto load_stage = [&](int kt, int st) {
        const int k0 = kt * BK;
        const int ka = (k0 < 1536) ? k0 : (k0 - 1536);  // A' = [hi | lo | hi]
        const int kb = (k0 < 768)  ? k0 : (k0 - 768);   // B' = [hi ; hi ; lo]
        const uint32_t aT = sbase + st * STAGE_BYTES;
        const uint32_t bT = aT + 16384;
        #pragma unroll
        for (int i = 0; i < 4; i++) {
            int idx = tid + i * 256;
            int row = idx >> 3, c = idx & 7;
            cp_async16(aT + SWZ((uint32_t)(row * 128 + c * 16)),
                       (const char*)(Ag + (long)row * KPHYS + ka) + c * 16);
        }
        #pragma unroll
        for (int i = 0; i < 4; i++) {
            int idx = tid + i * 256;
            int row = idx >> 3, c = idx & 7;
            cp_async16(bT + SWZ((uint32_t)(row * 128 + c * 16)),
                       (const char*)(Bg + (long)row * KPHYS + kb) + c * 16);
        }
        CP_ASYNC_COMMIT();
    };

    float acc[2][8][4];
    #pragma unroll
    for (int mm = 0; mm < 2; mm++)
        #pragma unroll
        for (int nt = 0; nt < 8; nt++)
            #pragma unroll
            for (int q = 0; q < 4; q++) acc[mm][nt][q] = 0.0f;

    load_stage(0, 0);
    load_stage(1, 1);

    // ldmatrix lane->address precomputation
    const int rA  = warp_m * 32 + (lane & 7) + ((lane >> 3) & 1) * 8;
    const int kbA = ((lane >> 4) & 1) * 16;
    const int rB  = warp_n * 64 + (lane & 7) + ((lane >> 4) & 1) * 8;
    const int kbB = ((lane >> 3) & 1) * 16;

    for (int kt = 0; kt < KT; kt++) {
        if (kt + 1 < KT) { CP_ASYNC_WAIT(1); } else { CP_ASYNC_WAIT(0); }
        __syncthreads();
        if (kt + 2 < KT) load_stage(kt + 2, (kt + 2) % STAGES);

        const uint32_t aT = sbase + (kt % STAGES) * STAGE_BYTES;
        const uint32_t bT = aT + 16384;

        #pragma unroll
        for (int ks = 0; ks < 4; ks++) {
            uint32_t a[2][4];
            ldsm_x4(a[0], aT + SWZ((uint32_t)(rA * 128 + ks * 32 + kbA)));
            ldsm_x4(a[1], aT + SWZ((uint32_t)((rA + 16) * 128 + ks * 32 + kbA)));
            uint32_t b[8][2];
            #pragma unroll
            for (int g = 0; g < 4; g++) {
                uint32_t t[4];
                ldsm_x4(t, bT + SWZ((uint32_t)((rB + g * 16) * 128 + ks * 32 + kbB)));
                b[2 * g][0]     = t[0]; b[2 * g][1]     = t[1];
                b[2 * g + 1][0] = t[2]; b[2 * g + 1][1] = t[3];
            }
            #pragma unroll
            for (int mm = 0; mm < 2; mm++)
                #pragma unroll
                for (int nt = 0; nt < 8; nt++)
                    mma16816(acc[mm][nt], a[mm], b[nt]);
        }
        __syncthreads();
    }

    // Epilogue: direct coalesced float2 stores
    const int gid = lane >> 2, tig = lane & 3;
    #pragma unroll
    for (int mm = 0; mm < 2; mm++) {
        const long mrow = (long)(m0 + warp_m * 32 + mm * 16 + gid);
        float* base0 = g_P + mrow * NPAD + n0 + warp_n * 64 + tig * 2;
        float* base1 = base0 + 8L * NPAD;
        #pragma unroll
        for (int nt = 0; nt < 8; nt++) {
            *(float2*)(base0 + nt * 8) = make_float2(acc[mm][nt][0], acc[mm][nt][1]);
            *(float2*)(base1 + nt * 8) = make_float2(acc[mm][nt][2], acc[mm][nt][3]);
        }
    }
}

// ============================================================================
// Fusion kernel: one warp per token
//   P row layout: [q(768) | k(768) | v(768) | h_self(192) | h_other(192)]
// ============================================================================
__global__ void __launch_bounds__(256) fusion_kernel(
    const float* __restrict__ x1, const float* __restrict__ x2,
    const float* __restrict__ b1, const float* __restrict__ W2,
    const float* __restrict__ b2, float* __restrict__ out) {
    const int token = blockIdx.x * 8 + (threadIdx.x >> 5);
    const int lane = threadIdx.x & 31;
    const long r  = token;
    const long ro = (r < MTOT / 2) ? (r + MTOT / 2) : (r - MTOT / 2);
    const float* Pr = g_P + r * NPAD;
    const float* Po = g_P + ro * NPAD;

    float ds = 0.0f, dc = 0.0f;
    #pragma unroll
    for (int i = 0; i < 24; i++) {
        int d = lane + i * 32;
        float q  = Pr[d];
        float ks = Pr[768 + d] + g_nk[d];
        float kc = Po[768 + d];
        ds += q * ks;
        dc += q * kc;
    }
    float hacc = 0.0f;
    #pragma unroll
    for (int i = 0; i < 6; i++) {
        int j = lane + i * 32;
        float hv = Pr[2304 + j] + Po[2496 + j] + b1[j];
        hv = 0.5f * hv * (1.0f + erff(hv * 0.7071067811865476f));  // exact gelu
        hacc += hv * W2[j];
    }
    #pragma unroll
    for (int o = 16; o; o >>= 1) {
        ds   += __shfl_xor_sync(0xFFFFFFFFu, ds, o);
        dc   += __shfl_xor_sync(0xFFFFFFFFu, dc, o);
        hacc += __shfl_xor_sync(0xFFFFFFFFu, hacc, o);
    }
    const float rel = 1.0f / (1.0f + expf(-(hacc + b2[0])));
    const float SCALE = 0.03608439182435161f;  // 768^-0.5
    float d0 = ds * SCALE;
    float d1 = dc * rel * SCALE;
    float mx = fmaxf(d0, d1);
    float e0 = expf(d0 - mx), e1 = expf(d1 - mx);
    float inv = 1.0f / (e0 + e1);
    float w0 = e0 * inv, w1 = e1 * inv;

    const float* xsrc = (r < MTOT / 2) ? (x1 + r * DIM)
                                       : (x2 + (r - MTOT / 2) * DIM);
    float* orow = out + r * DIM;
    #pragma unroll
    for (int i = 0; i < 24; i++) {
        int d = lane + i * 32;
        orow[d] = xsrc[d] + w0 * Pr[1536 + d] + w1 * Po[1536 + d];
    }
}

// ============================================================================
// Launch
// ============================================================================
extern "C" void kernel_launch(void* const* d_in, const int* in_sizes, int n_in,
                              void* d_out, int out_size) {
    const float* x1    = (const float*)d_in[0];
    const float* x2    = (const float*)d_in[1];
    const float* Wq    = (const float*)d_in[2];
    const float* Wk    = (const float*)d_in[3];
    const float* Wv    = (const float*)d_in[4];
    const float* noise = (const float*)d_in[5];
    const float* W1    = (const float*)d_in[6];
    const float* b1    = (const float*)d_in[7];
    const float* W2    = (const float*)d_in[8];
    const float* b2    = (const float*)d_in[9];
    float* out = (float*)d_out;

    cudaFuncSetAttribute(gemm_kernel,
                         cudaFuncAttributeMaxDynamicSharedMemorySize, SM_TOTAL);

    prep_w_kernel<<<NPAD, 256>>>(Wq, Wk, Wv, W1);
    prep_x_kernel<<<MTOT, 256>>>(x1, x2);
    nk_kernel<<<6, 128>>>(noise, Wk);

    dim3 grid(NPAD / BN, MTOT / BM);   // (21, 512)
    gemm_kernel<<<grid, 256, SM_TOTAL>>>();

    fusion_kernel<<<MTOT / 8, 256>>>(x1, x2, b1, W2, b2, out);
}

// round 4
// speedup vs baseline: 1.3260x; 1.3260x over previous
#include <cuda_runtime.h>
#include <cuda_fp16.h>
#include <cstdint>
#include <math.h>

// ============================================================================
// Problem constants
//   x1,x2: [32,1024,768]  -> stacked X: [65536, 768]
//   P = X @ [Wq | Wk | Wv | W1a | W1b]  : [65536, 2688]
//   fp16 2-term split folded into K:
//     A' = [Xhi | Xlo]  (K=1536 physical),  B' = [W ; W] (K=768 physical,
//     kb = k0 mod 768).  Only W's fp16 rounding survives (~2^-11).
// ============================================================================
#define MTOT   65536
#define DIM    768
#define NPAD   2688            // 21 * 128, exact
#define KPA    1536            // A physical K (hi|lo)
#define KPB    768             // B physical K
#define KEFF   1536

#define BM 128
#define BN 128
#define BK 64
#define KT (KEFF / BK)         // 24
#define STAGES 3

// ============================================================================
// Scratch (__device__ globals)
// ============================================================================
__device__ __half g_Xc[(long)MTOT * KPA];   // [65536][1536] fp16 (hi|lo)
__device__ __half g_Wc[(long)NPAD * KPB];   // [2688][768]   fp16, n-major
__device__ float  g_P [(long)MTOT * NPAD];  // [65536][2688] fp32
__device__ float  g_nk[DIM];                // noise @ Wk

// ============================================================================
// Helpers
// ============================================================================
__device__ __forceinline__ uint32_t smem_to_u32(const void* smem_ptr) {
    uint32_t addr;
    asm("{ .reg .u64 tmp; cvta.to.shared.u64 tmp, %1; cvt.u32.u64 %0, tmp; }"
        : "=r"(addr) : "l"(smem_ptr));
    return addr;
}

#define SWZ(byte_offset) ((byte_offset) ^ ((((uint32_t)(byte_offset)) >> 3) & 0x70))

__device__ __forceinline__ void cp_async16(uint32_t dst_smem, const void* src) {
    asm volatile("cp.async.cg.shared.global [%0], [%1], 16;"
        :: "r"(dst_smem), "l"(src) : "memory");
}
#define CP_ASYNC_COMMIT()  asm volatile("cp.async.commit_group;" ::: "memory")
#define CP_ASYNC_WAIT(N)   asm volatile("cp.async.wait_group %0;" :: "n"(N) : "memory")

__device__ __forceinline__ void ldsm_x4(uint32_t* r, uint32_t addr) {
    asm volatile("ldmatrix.sync.aligned.m8n8.x4.shared.b16 {%0,%1,%2,%3}, [%4];"
        : "=r"(r[0]), "=r"(r[1]), "=r"(r[2]), "=r"(r[3]) : "r"(addr));
}

__device__ __forceinline__ void mma16816(float* c, const uint32_t* a, const uint32_t* b) {
    asm volatile(
        "mma.sync.aligned.m16n8k16.row.col.f32.f16.f16.f32 "
        "{%0,%1,%2,%3}, {%4,%5,%6,%7}, {%8,%9}, {%0,%1,%2,%3};"
        : "+f"(c[0]), "+f"(c[1]), "+f"(c[2]), "+f"(c[3])
        : "r"(a[0]), "r"(a[1]), "r"(a[2]), "r"(a[3]), "r"(b[0]), "r"(b[1]));
}

// ============================================================================
// Prep kernels
// ============================================================================
__global__ void prep_x_kernel(const float* __restrict__ x1,
                              const float* __restrict__ x2) {
    long r = blockIdx.x;
    const float* src = (r < (MTOT / 2)) ? (x1 + r * DIM)
                                        : (x2 + (r - MTOT / 2) * DIM);
    __half* dst = g_Xc + r * KPA;
    for (int c = threadIdx.x; c < DIM; c += blockDim.x) {
        float v = src[c];
        __half hi = __float2half(v);
        dst[c] = hi;
        dst[DIM + c] = __float2half(v - __half2float(hi));
    }
}

__global__ void prep_w_kernel(const float* __restrict__ Wq,
                              const float* __restrict__ Wk,
                              const float* __restrict__ Wv,
                              const float* __restrict__ W1) {
    int n = blockIdx.x;  // 0..NPAD-1
    __half* dst = g_Wc + (long)n * KPB;
    for (int j = threadIdx.x; j < DIM; j += blockDim.x) {
        float w;
        if      (n < 768)  w = Wq[j * 768 + n];
        else if (n < 1536) w = Wk[j * 768 + (n - 768)];
        else if (n < 2304) w = Wv[j * 768 + (n - 1536)];
        else if (n < 2496) w = W1[j * 192 + (n - 2304)];          // W1a (rows 0..767)
        else               w = W1[(768 + j) * 192 + (n - 2496)];  // W1b (rows 768..1535)
        dst[j] = __float2half(w);
    }
}

__global__ void nk_kernel(const float* __restrict__ noise,
                          const float* __restrict__ Wk) {
    int d = blockIdx.x * blockDim.x + threadIdx.x;
    if (d >= DIM) return;
    float acc = 0.0f;
    for (int j = 0; j < DIM; j++) acc += noise[j] * Wk[j * 768 + d];
    g_nk[d] = acc;
}

// ============================================================================
// GEMM: P[65536, 2688] = A'[65536, 1536] @ B'[2688, 1536]^T  (fp16 -> fp32)
// mma.sync.m16n8k16 path. 256 threads, 8 warps (4 m x 2 n).
// smem: STAGES x (A 16KB + B 16KB), SW128 swizzle, cp.async 3-stage pipeline.
// ============================================================================
#define STAGE_BYTES 32768
#define SM_TOTAL    (STAGES * STAGE_BYTES)

__global__ void __launch_bounds__(256, 2) gemm_kernel() {
    extern __shared__ char smem[];
    const uint32_t sbase = smem_to_u32(smem);
    const int tid    = threadIdx.x;
    const int wid    = tid >> 5;
    const int lane   = tid & 31;
    const int warp_m = wid & 3;   // 0..3, 32 rows each
    const int warp_n = wid >> 2;  // 0..1, 64 cols each
    const int m0 = blockIdx.y * BM;
    const int n0 = blockIdx.x * BN;

    const __half* Ag = g_Xc + (long)m0 * KPA;
    const __half* Bg = g_Wc + (long)n0 * KPB;

    auto load_stage = [&](int kt, int st) {
        const int k0 = kt * BK;
        const int ka = k0;                              // A' = [hi | lo], direct
        const int kb = (k0 < 768) ? k0 : (k0 - 768);    // B' = [W ; W]
        const uint32_t aT = sbase + st * STAGE_BYTES;
        const uint32_t bT = aT + 16384;
        #pragma unroll
        for (int i = 0; i < 4; i++) {
            int idx = tid + i * 256;
            int row = idx >> 3, c = idx & 7;
            cp_async16(aT + SWZ((uint32_t)(row * 128 + c * 16)),
                       (const char*)(Ag + (long)row * KPA + ka) + c * 16);
        }
        #pragma unroll
        for (int i = 0; i < 4; i++) {
            int idx = tid + i * 256;
            int row = idx >> 3, c = idx & 7;
            cp_async16(bT + SWZ((uint32_t)(row * 128 + c * 16)),
                       (const char*)(Bg + (long)row * KPB + kb) + c * 16);
        }
        CP_ASYNC_COMMIT();
    };

    float acc[2][8][4];
    #pragma unroll
    for (int mm = 0; mm < 2; mm++)
        #pragma unroll
        for (int nt = 0; nt < 8; nt++)
            #pragma unroll
            for (int q = 0; q < 4; q++) acc[mm][nt][q] = 0.0f;

    load_stage(0, 0);
    load_stage(1, 1);

    // ldmatrix lane->address precomputation
    const int rA  = warp_m * 32 + (lane & 7) + ((lane >> 3) & 1) * 8;
    const int kbA = ((lane >> 4) & 1) * 16;
    const int rB  = warp_n * 64 + (lane & 7) + ((lane >> 4) & 1) * 8;
    const int kbB = ((lane >> 3) & 1) * 16;

    for (int kt = 0; kt < KT; kt++) {
        if (kt + 1 < KT) { CP_ASYNC_WAIT(1); } else { CP_ASYNC_WAIT(0); }
        __syncthreads();
        if (kt + 2 < KT) load_stage(kt + 2, (kt + 2) % STAGES);

        const uint32_t aT = sbase + (kt % STAGES) * STAGE_BYTES;
        const uint32_t bT = aT + 16384;

        #pragma unroll
        for (int ks = 0; ks < 4; ks++) {
            uint32_t a[2][4];
            ldsm_x4(a[0], aT + SWZ((uint32_t)(rA * 128 + ks * 32 + kbA)));
            ldsm_x4(a[1], aT + SWZ((uint32_t)((rA + 16) * 128 + ks * 32 + kbA)));
            uint32_t b[8][2];
            #pragma unroll
            for (int g = 0; g < 4; g++) {
                uint32_t t[4];
                ldsm_x4(t, bT + SWZ((uint32_t)((rB + g * 16) * 128 + ks * 32 + kbB)));
                b[2 * g][0]     = t[0]; b[2 * g][1]     = t[1];
                b[2 * g + 1][0] = t[2]; b[2 * g + 1][1] = t[3];
            }
            #pragma unroll
            for (int mm = 0; mm < 2; mm++)
                #pragma unroll
                for (int nt = 0; nt < 8; nt++)
                    mma16816(acc[mm][nt], a[mm], b[nt]);
        }
        __syncthreads();
    }

    // Epilogue: direct coalesced float2 stores
    const int gid = lane >> 2, tig = lane & 3;
    #pragma unroll
    for (int mm = 0; mm < 2; mm++) {
        const long mrow = (long)(m0 + warp_m * 32 + mm * 16 + gid);
        float* base0 = g_P + mrow * NPAD + n0 + warp_n * 64 + tig * 2;
        float* base1 = base0 + 8L * NPAD;
        #pragma unroll
        for (int nt = 0; nt < 8; nt++) {
            *(float2*)(base0 + nt * 8) = make_float2(acc[mm][nt][0], acc[mm][nt][1]);
            *(float2*)(base1 + nt * 8) = make_float2(acc[mm][nt][2], acc[mm][nt][3]);
        }
    }
}

// ============================================================================
// Fusion kernel: one warp per token
//   P row layout: [q(768) | k(768) | v(768) | h_self(192) | h_other(192)]
// ============================================================================
__global__ void __launch_bounds__(256) fusion_kernel(
    const float* __restrict__ x1, const float* __restrict__ x2,
    const float* __restrict__ b1, const float* __restrict__ W2,
    const float* __restrict__ b2, float* __restrict__ out) {
    const int token = blockIdx.x * 8 + (threadIdx.x >> 5);
    const int lane = threadIdx.x & 31;
    const long r  = token;
    const long ro = (r < MTOT / 2) ? (r + MTOT / 2) : (r - MTOT / 2);
    const float* Pr = g_P + r * NPAD;
    const float* Po = g_P + ro * NPAD;

    float ds = 0.0f, dc = 0.0f;
    #pragma unroll
    for (int i = 0; i < 24; i++) {
        int d = lane + i * 32;
        float q  = Pr[d];
        float ks = Pr[768 + d] + g_nk[d];
        float kc = Po[768 + d];
        ds += q * ks;
        dc += q * kc;
    }
    float hacc = 0.0f;
    #pragma unroll
    for (int i = 0; i < 6; i++) {
        int j = lane + i * 32;
        float hv = Pr[2304 + j] + Po[2496 + j] + b1[j];
        hv = 0.5f * hv * (1.0f + erff(hv * 0.7071067811865476f));  // exact gelu
        hacc += hv * W2[j];
    }
    #pragma unroll
    for (int o = 16; o; o >>= 1) {
        ds   += __shfl_xor_sync(0xFFFFFFFFu, ds, o);
        dc   += __shfl_xor_sync(0xFFFFFFFFu, dc, o);
        hacc += __shfl_xor_sync(0xFFFFFFFFu, hacc, o);
    }
    const float rel = 1.0f / (1.0f + expf(-(hacc + b2[0])));
    const float SCALE = 0.03608439182435161f;  // 768^-0.5
    float d0 = ds * SCALE;
    float d1 = dc * rel * SCALE;
    float mx = fmaxf(d0, d1);
    float e0 = expf(d0 - mx), e1 = expf(d1 - mx);
    float inv = 1.0f / (e0 + e1);
    float w0 = e0 * inv, w1 = e1 * inv;

    const float* xsrc = (r < MTOT / 2) ? (x1 + r * DIM)
                                       : (x2 + (r - MTOT / 2) * DIM);
    float* orow = out + r * DIM;
    #pragma unroll
    for (int i = 0; i < 24; i++) {
        int d = lane + i * 32;
        orow[d] = xsrc[d] + w0 * Pr[1536 + d] + w1 * Po[1536 + d];
    }
}

// ============================================================================
// Launch
// ============================================================================
extern "C" void kernel_launch(void* const* d_in, const int* in_sizes, int n_in,
                              void* d_out, int out_size) {
    const float* x1    = (const float*)d_in[0];
    const float* x2    = (const float*)d_in[1];
    const float* Wq    = (const float*)d_in[2];
    const float* Wk    = (const float*)d_in[3];
    const float* Wv    = (const float*)d_in[4];
    const float* noise = (const float*)d_in[5];
    const float* W1    = (const float*)d_in[6];
    const float* b1    = (const float*)d_in[7];
    const float* W2    = (const float*)d_in[8];
    const float* b2    = (const float*)d_in[9];
    float* out = (float*)d_out;

    cudaFuncSetAttribute(gemm_kernel,
                         cudaFuncAttributeMaxDynamicSharedMemorySize, SM_TOTAL);

    prep_w_kernel<<<NPAD, 256>>>(Wq, Wk, Wv, W1);
    prep_x_kernel<<<MTOT, 256>>>(x1, x2);
    nk_kernel<<<6, 128>>>(noise, Wk);

    dim3 grid(NPAD / BN, MTOT / BM);   // (21, 512)
    gemm_kernel<<<grid, 256, SM_TOTAL>>>();

    fusion_kernel<<<MTOT / 8, 256>>>(x1, x2, b1, W2, b2, out);
}

// round 5
// speedup vs baseline: 2.0125x; 1.5178x over previous
#include <cuda_runtime.h>
#include <cuda_fp16.h>
#include <cstdint>
#include <math.h>

// ============================================================================
// Problem constants
//   x1,x2: [32,1024,768]  -> stacked X: [65536, 768]
//   P = X @ [Wq | Wk | Wv | W1a | W1b]  : [65536, 2688]
//   Plain fp16 GEMM (X and W both rounded to fp16): measured error budget
//   ~1.2e-4 vs 1e-3 gate. K = 768.
// ============================================================================
#define MTOT   65536
#define DIM    768
#define NPAD   2688            // 21 * 128, exact
#define KPA    768             // A physical K
#define KPB    768             // B physical K
#define KEFF   768

#define BM 128
#define BN 128
#define BK 64
#define KT (KEFF / BK)         // 12
#define STAGES 3

// ============================================================================
// Scratch (__device__ globals)
// ============================================================================
__device__ __half g_Xc[(long)MTOT * KPA];   // [65536][768] fp16
__device__ __half g_Wc[(long)NPAD * KPB];   // [2688][768]  fp16, n-major
__device__ float  g_P [(long)MTOT * NPAD];  // [65536][2688] fp32
__device__ float  g_nk[DIM];                // noise @ Wk

// ============================================================================
// Helpers
// ============================================================================
__device__ __forceinline__ uint32_t smem_to_u32(const void* smem_ptr) {
    uint32_t addr;
    asm("{ .reg .u64 tmp; cvta.to.shared.u64 tmp, %1; cvt.u32.u64 %0, tmp; }"
        : "=r"(addr) : "l"(smem_ptr));
    return addr;
}

#define SWZ(byte_offset) ((byte_offset) ^ ((((uint32_t)(byte_offset)) >> 3) & 0x70))

__device__ __forceinline__ void cp_async16(uint32_t dst_smem, const void* src) {
    asm volatile("cp.async.cg.shared.global [%0], [%1], 16;"
        :: "r"(dst_smem), "l"(src) : "memory");
}
#define CP_ASYNC_COMMIT()  asm volatile("cp.async.commit_group;" ::: "memory")
#define CP_ASYNC_WAIT(N)   asm volatile("cp.async.wait_group %0;" :: "n"(N) : "memory")

__device__ __forceinline__ void ldsm_x4(uint32_t* r, uint32_t addr) {
    asm volatile("ldmatrix.sync.aligned.m8n8.x4.shared.b16 {%0,%1,%2,%3}, [%4];"
        : "=r"(r[0]), "=r"(r[1]), "=r"(r[2]), "=r"(r[3]) : "r"(addr));
}

__device__ __forceinline__ void mma16816(float* c, const uint32_t* a, const uint32_t* b) {
    asm volatile(
        "mma.sync.aligned.m16n8k16.row.col.f32.f16.f16.f32 "
        "{%0,%1,%2,%3}, {%4,%5,%6,%7}, {%8,%9}, {%0,%1,%2,%3};"
        : "+f"(c[0]), "+f"(c[1]), "+f"(c[2]), "+f"(c[3])
        : "r"(a[0]), "r"(a[1]), "r"(a[2]), "r"(a[3]), "r"(b[0]), "r"(b[1]));
}

// ============================================================================
// Prep kernels
// ============================================================================
__global__ void prep_x_kernel(const float* __restrict__ x1,
                              const float* __restrict__ x2) {
    long r = blockIdx.x;
    const float* src = (r < (MTOT / 2)) ? (x1 + r * DIM)
                                        : (x2 + (r - MTOT / 2) * DIM);
    __half* dst = g_Xc + r * KPA;
    for (int c = threadIdx.x; c < DIM; c += blockDim.x)
        dst[c] = __float2half(src[c]);
}

__global__ void prep_w_kernel(const float* __restrict__ Wq,
                              const float* __restrict__ Wk,
                              const float* __restrict__ Wv,
                              const float* __restrict__ W1) {
    int n = blockIdx.x;  // 0..NPAD-1
    __half* dst = g_Wc + (long)n * KPB;
    for (int j = threadIdx.x; j < DIM; j += blockDim.x) {
        float w;
        if      (n < 768)  w = Wq[j * 768 + n];
        else if (n < 1536) w = Wk[j * 768 + (n - 768)];
        else if (n < 2304) w = Wv[j * 768 + (n - 1536)];
        else if (n < 2496) w = W1[j * 192 + (n - 2304)];          // W1a (rows 0..767)
        else               w = W1[(768 + j) * 192 + (n - 2496)];  // W1b (rows 768..1535)
        dst[j] = __float2half(w);
    }
}

__global__ void nk_kernel(const float* __restrict__ noise,
                          const float* __restrict__ Wk) {
    int d = blockIdx.x * blockDim.x + threadIdx.x;
    if (d >= DIM) return;
    float acc = 0.0f;
    for (int j = 0; j < DIM; j++) acc += noise[j] * Wk[j * 768 + d];
    g_nk[d] = acc;
}

// ============================================================================
// GEMM: P[65536, 2688] = A[65536, 768] @ B[2688, 768]^T  (fp16 -> fp32)
// mma.sync.m16n8k16 path. 256 threads, 8 warps (4 m x 2 n).
// smem: STAGES x (A 16KB + B 16KB), SW128 swizzle, cp.async 3-stage pipeline.
// One barrier per k-tile (trailing barrier proven redundant with 3 stages).
// ============================================================================
#define STAGE_BYTES 32768
#define SM_TOTAL    (STAGES * STAGE_BYTES)

__global__ void __launch_bounds__(256, 2) gemm_kernel() {
    extern __shared__ char smem[];
    const uint32_t sbase = smem_to_u32(smem);
    const int tid    = threadIdx.x;
    const int wid    = tid >> 5;
    const int lane   = tid & 31;
    const int warp_m = wid & 3;   // 0..3, 32 rows each
    const int warp_n = wid >> 2;  // 0..1, 64 cols each
    const int m0 = blockIdx.y * BM;
    const int n0 = blockIdx.x * BN;

    const __half* Ag = g_Xc + (long)m0 * KPA;
    const __half* Bg = g_Wc + (long)n0 * KPB;

    auto load_stage = [&](int kt, int st) {
        const int k0 = kt * BK;
        const uint32_t aT = sbase + st * STAGE_BYTES;
        const uint32_t bT = aT + 16384;
        #pragma unroll
        for (int i = 0; i < 4; i++) {
            int idx = tid + i * 256;
            int row = idx >> 3, c = idx & 7;
            cp_async16(aT + SWZ((uint32_t)(row * 128 + c * 16)),
                       (const char*)(Ag + (long)row * KPA + k0) + c * 16);
        }
        #pragma unroll
        for (int i = 0; i < 4; i++) {
            int idx = tid + i * 256;
            int row = idx >> 3, c = idx & 7;
            cp_async16(bT + SWZ((uint32_t)(row * 128 + c * 16)),
                       (const char*)(Bg + (long)row * KPB + k0) + c * 16);
        }
        CP_ASYNC_COMMIT();
    };

    float acc[2][8][4];
    #pragma unroll
    for (int mm = 0; mm < 2; mm++)
        #pragma unroll
        for (int nt = 0; nt < 8; nt++)
            #pragma unroll
            for (int q = 0; q < 4; q++) acc[mm][nt][q] = 0.0f;

    load_stage(0, 0);
    load_stage(1, 1);

    // ldmatrix lane->address precomputation
    const int rA  = warp_m * 32 + (lane & 7) + ((lane >> 3) & 1) * 8;
    const int kbA = ((lane >> 4) & 1) * 16;
    const int rB  = warp_n * 64 + (lane & 7) + ((lane >> 4) & 1) * 8;
    const int kbB = ((lane >> 3) & 1) * 16;

    for (int kt = 0; kt < KT; kt++) {
        if (kt + 1 < KT) { CP_ASYNC_WAIT(1); } else { CP_ASYNC_WAIT(0); }
        __syncthreads();
        if (kt + 2 < KT) load_stage(kt + 2, (kt + 2) % STAGES);

        const uint32_t aT = sbase + (kt % STAGES) * STAGE_BYTES;
        const uint32_t bT = aT + 16384;

        #pragma unroll
        for (int ks = 0; ks < 4; ks++) {
            uint32_t a[2][4];
            ldsm_x4(a[0], aT + SWZ((uint32_t)(rA * 128 + ks * 32 + kbA)));
            ldsm_x4(a[1], aT + SWZ((uint32_t)((rA + 16) * 128 + ks * 32 + kbA)));
            uint32_t b[8][2];
            #pragma unroll
            for (int g = 0; g < 4; g++) {
                uint32_t t[4];
                ldsm_x4(t, bT + SWZ((uint32_t)((rB + g * 16) * 128 + ks * 32 + kbB)));
                b[2 * g][0]     = t[0]; b[2 * g][1]     = t[1];
                b[2 * g + 1][0] = t[2]; b[2 * g + 1][1] = t[3];
            }
            #pragma unroll
            for (int mm = 0; mm < 2; mm++)
                #pragma unroll
                for (int nt = 0; nt < 8; nt++)
                    mma16816(acc[mm][nt], a[mm], b[nt]);
        }
        // no trailing barrier: stage (kt+2)%3 was last read at iteration kt-1,
        // strictly before the barrier at iteration kt that precedes its refill.
    }

    // Epilogue: direct coalesced float2 stores
    const int gid = lane >> 2, tig = lane & 3;
    #pragma unroll
    for (int mm = 0; mm < 2; mm++) {
        const long mrow = (long)(m0 + warp_m * 32 + mm * 16 + gid);
        float* base0 = g_P + mrow * NPAD + n0 + warp_n * 64 + tig * 2;
        float* base1 = base0 + 8L * NPAD;
        #pragma unroll
        for (int nt = 0; nt < 8; nt++) {
            *(float2*)(base0 + nt * 8) = make_float2(acc[mm][nt][0], acc[mm][nt][1]);
            *(float2*)(base1 + nt * 8) = make_float2(acc[mm][nt][2], acc[mm][nt][3]);
        }
    }
}

// ============================================================================
// Fusion kernel: one warp per token
//   P row layout: [q(768) | k(768) | v(768) | h_self(192) | h_other(192)]
// ============================================================================
__global__ void __launch_bounds__(256) fusion_kernel(
    const float* __restrict__ x1, const float* __restrict__ x2,
    const float* __restrict__ b1, const float* __restrict__ W2,
    const float* __restrict__ b2, float* __restrict__ out) {
    const int token = blockIdx.x * 8 + (threadIdx.x >> 5);
    const int lane = threadIdx.x & 31;
    const long r  = token;
    const long ro = (r < MTOT / 2) ? (r + MTOT / 2) : (r - MTOT / 2);
    const float* Pr = g_P + r * NPAD;
    const float* Po = g_P + ro * NPAD;

    float ds = 0.0f, dc = 0.0f;
    #pragma unroll
    for (int i = 0; i < 24; i++) {
        int d = lane + i * 32;
        float q  = Pr[d];
        float ks = Pr[768 + d] + g_nk[d];
        float kc = Po[768 + d];
        ds += q * ks;
        dc += q * kc;
    }
    float hacc = 0.0f;
    #pragma unroll
    for (int i = 0; i < 6; i++) {
        int j = lane + i * 32;
        float hv = Pr[2304 + j] + Po[2496 + j] + b1[j];
        hv = 0.5f * hv * (1.0f + erff(hv * 0.7071067811865476f));  // exact gelu
        hacc += hv * W2[j];
    }
    #pragma unroll
    for (int o = 16; o; o >>= 1) {
        ds   += __shfl_xor_sync(0xFFFFFFFFu, ds, o);
        dc   += __shfl_xor_sync(0xFFFFFFFFu, dc, o);
        hacc += __shfl_xor_sync(0xFFFFFFFFu, hacc, o);
    }
    const float rel = 1.0f / (1.0f + expf(-(hacc + b2[0])));
    const float SCALE = 0.03608439182435161f;  // 768^-0.5
    float d0 = ds * SCALE;
    float d1 = dc * rel * SCALE;
    float mx = fmaxf(d0, d1);
    float e0 = expf(d0 - mx), e1 = expf(d1 - mx);
    float inv = 1.0f / (e0 + e1);
    float w0 = e0 * inv, w1 = e1 * inv;

    const float* xsrc = (r < MTOT / 2) ? (x1 + r * DIM)
                                       : (x2 + (r - MTOT / 2) * DIM);
    float* orow = out + r * DIM;
    #pragma unroll
    for (int i = 0; i < 24; i++) {
        int d = lane + i * 32;
        orow[d] = xsrc[d] + w0 * Pr[1536 + d] + w1 * Po[1536 + d];
    }
}

// ============================================================================
// Launch
// ============================================================================
extern "C" void kernel_launch(void* const* d_in, const int* in_sizes, int n_in,
                              void* d_out, int out_size) {
    const float* x1    = (const float*)d_in[0];
    const float* x2    = (const float*)d_in[1];
    const float* Wq    = (const float*)d_in[2];
    const float* Wk    = (const float*)d_in[3];
    const float* Wv    = (const float*)d_in[4];
    const float* noise = (const float*)d_in[5];
    const float* W1    = (const float*)d_in[6];
    const float* b1    = (const float*)d_in[7];
    const float* W2    = (const float*)d_in[8];
    const float* b2    = (const float*)d_in[9];
    float* out = (float*)d_out;

    cudaFuncSetAttribute(gemm_kernel,
                         cudaFuncAttributeMaxDynamicSharedMemorySize, SM_TOTAL);

    prep_w_kernel<<<NPAD, 256>>>(Wq, Wk, Wv, W1);
    prep_x_kernel<<<MTOT, 256>>>(x1, x2);
    nk_kernel<<<6, 128>>>(noise, Wk);

    dim3 grid(NPAD / BN, MTOT / BM);   // (21, 512)
    gemm_kernel<<<grid, 256, SM_TOTAL>>>();

    fusion_kernel<<<MTOT / 8, 256>>>(x1, x2, b1, W2, b2, out);
}

// round 6
// speedup vs baseline: 2.2083x; 1.0973x over previous
#include <cuda_runtime.h>
#include <cuda_fp16.h>
#include <cstdint>
#include <math.h>

// ============================================================================
// Problem constants
//   x1,x2: [32,1024,768]  -> stacked X: [65536, 768]
//   P = X @ [Wq | Wk | Wv | W1a | W1b]  : [65536, 2688]
//   fp16 GEMM (K=768), P stored fp16 (error budget ~1.5e-4 vs 1e-3 gate).
// ============================================================================
#define MTOT   65536
#define DIM    768
#define NPAD   2688            // 21 * 128, exact
#define KPA    768
#define KPB    768
#define KEFF   768

#define BM 128
#define BN 128
#define BK 64
#define KT (KEFF / BK)         // 12
#define STAGES 3

// ============================================================================
// Scratch (__device__ globals)
// ============================================================================
__device__ __half g_Xc[(long)MTOT * KPA];   // [65536][768] fp16
__device__ __half g_Wc[(long)NPAD * KPB];   // [2688][768]  fp16, n-major
__device__ __half g_P [(long)MTOT * NPAD];  // [65536][2688] fp16
__device__ float  g_nk[DIM];                // noise @ Wk

// ============================================================================
// Helpers
// ============================================================================
__device__ __forceinline__ uint32_t smem_to_u32(const void* smem_ptr) {
    uint32_t addr;
    asm("{ .reg .u64 tmp; cvta.to.shared.u64 tmp, %1; cvt.u32.u64 %0, tmp; }"
        : "=r"(addr) : "l"(smem_ptr));
    return addr;
}

#define SWZ(byte_offset) ((byte_offset) ^ ((((uint32_t)(byte_offset)) >> 3) & 0x70))

__device__ __forceinline__ void cp_async16(uint32_t dst_smem, const void* src) {
    asm volatile("cp.async.cg.shared.global [%0], [%1], 16;"
        :: "r"(dst_smem), "l"(src) : "memory");
}
#define CP_ASYNC_COMMIT()  asm volatile("cp.async.commit_group;" ::: "memory")
#define CP_ASYNC_WAIT(N)   asm volatile("cp.async.wait_group %0;" :: "n"(N) : "memory")

__device__ __forceinline__ void ldsm_x4(uint32_t* r, uint32_t addr) {
    asm volatile("ldmatrix.sync.aligned.m8n8.x4.shared.b16 {%0,%1,%2,%3}, [%4];"
        : "=r"(r[0]), "=r"(r[1]), "=r"(r[2]), "=r"(r[3]) : "r"(addr));
}

__device__ __forceinline__ void mma16816(float* c, const uint32_t* a, const uint32_t* b) {
    asm volatile(
        "mma.sync.aligned.m16n8k16.row.col.f32.f16.f16.f32 "
        "{%0,%1,%2,%3}, {%4,%5,%6,%7}, {%8,%9}, {%0,%1,%2,%3};"
        : "+f"(c[0]), "+f"(c[1]), "+f"(c[2]), "+f"(c[3])
        : "r"(a[0]), "r"(a[1]), "r"(a[2]), "r"(a[3]), "r"(b[0]), "r"(b[1]));
}

// ============================================================================
// Prep kernels
// ============================================================================
__global__ void prep_x_kernel(const float* __restrict__ x1,
                              const float* __restrict__ x2) {
    long r = blockIdx.x;
    const float* src = (r < (MTOT / 2)) ? (x1 + r * DIM)
                                        : (x2 + (r - MTOT / 2) * DIM);
    __half* dst = g_Xc + r * KPA;
    for (int c = threadIdx.x; c < DIM; c += blockDim.x)
        dst[c] = __float2half(src[c]);
}

__global__ void prep_w_kernel(const float* __restrict__ Wq,
                              const float* __restrict__ Wk,
                              const float* __restrict__ Wv,
                              const float* __restrict__ W1) {
    int n = blockIdx.x;  // 0..NPAD-1
    __half* dst = g_Wc + (long)n * KPB;
    for (int j = threadIdx.x; j < DIM; j += blockDim.x) {
        float w;
        if      (n < 768)  w = Wq[j * 768 + n];
        else if (n < 1536) w = Wk[j * 768 + (n - 768)];
        else if (n < 2304) w = Wv[j * 768 + (n - 1536)];
        else if (n < 2496) w = W1[j * 192 + (n - 2304)];          // W1a (rows 0..767)
        else               w = W1[(768 + j) * 192 + (n - 2496)];  // W1b (rows 768..1535)
        dst[j] = __float2half(w);
    }
}

__global__ void nk_kernel(const float* __restrict__ noise,
                          const float* __restrict__ Wk) {
    int d = blockIdx.x * blockDim.x + threadIdx.x;
    if (d >= DIM) return;
    float acc = 0.0f;
    for (int j = 0; j < DIM; j++) acc += noise[j] * Wk[j * 768 + d];
    g_nk[d] = acc;
}

// ============================================================================
// GEMM: P[65536, 2688] = A[65536, 768] @ B[2688, 768]^T  (fp16 -> fp32 -> fp16)
// mma.sync.m16n8k16 path. 256 threads, 8 warps (4 m x 2 n).
// smem: STAGES x (A 16KB + B 16KB), SW128 swizzle, cp.async 3-stage pipeline.
// ============================================================================
#define STAGE_BYTES 32768
#define SM_TOTAL    (STAGES * STAGE_BYTES)

__global__ void __launch_bounds__(256, 2) gemm_kernel() {
    extern __shared__ char smem[];
    const uint32_t sbase = smem_to_u32(smem);
    const int tid    = threadIdx.x;
    const int wid    = tid >> 5;
    const int lane   = tid & 31;
    const int warp_m = wid & 3;   // 0..3, 32 rows each
    const int warp_n = wid >> 2;  // 0..1, 64 cols each
    const int m0 = blockIdx.y * BM;
    const int n0 = blockIdx.x * BN;

    const __half* Ag = g_Xc + (long)m0 * KPA;
    const __half* Bg = g_Wc + (long)n0 * KPB;

    auto load_stage = [&](int kt, int st) {
        const int k0 = kt * BK;
        const uint32_t aT = sbase + st * STAGE_BYTES;
        const uint32_t bT = aT + 16384;
        #pragma unroll
        for (int i = 0; i < 4; i++) {
            int idx = tid + i * 256;
            int row = idx >> 3, c = idx & 7;
            cp_async16(aT + SWZ((uint32_t)(row * 128 + c * 16)),
                       (const char*)(Ag + (long)row * KPA + k0) + c * 16);
        }
        #pragma unroll
        for (int i = 0; i < 4; i++) {
            int idx = tid + i * 256;
            int row = idx >> 3, c = idx & 7;
            cp_async16(bT + SWZ((uint32_t)(row * 128 + c * 16)),
                       (const char*)(Bg + (long)row * KPB + k0) + c * 16);
        }
        CP_ASYNC_COMMIT();
    };

    float acc[2][8][4];
    #pragma unroll
    for (int mm = 0; mm < 2; mm++)
        #pragma unroll
        for (int nt = 0; nt < 8; nt++)
            #pragma unroll
            for (int q = 0; q < 4; q++) acc[mm][nt][q] = 0.0f;

    load_stage(0, 0);
    load_stage(1, 1);

    // ldmatrix lane->address precomputation
    const int rA  = warp_m * 32 + (lane & 7) + ((lane >> 3) & 1) * 8;
    const int kbA = ((lane >> 4) & 1) * 16;
    const int rB  = warp_n * 64 + (lane & 7) + ((lane >> 4) & 1) * 8;
    const int kbB = ((lane >> 3) & 1) * 16;

    for (int kt = 0; kt < KT; kt++) {
        if (kt + 1 < KT) { CP_ASYNC_WAIT(1); } else { CP_ASYNC_WAIT(0); }
        __syncthreads();
        if (kt + 2 < KT) load_stage(kt + 2, (kt + 2) % STAGES);

        const uint32_t aT = sbase + (kt % STAGES) * STAGE_BYTES;
        const uint32_t bT = aT + 16384;

        #pragma unroll
        for (int ks = 0; ks < 4; ks++) {
            uint32_t a[2][4];
            ldsm_x4(a[0], aT + SWZ((uint32_t)(rA * 128 + ks * 32 + kbA)));
            ldsm_x4(a[1], aT + SWZ((uint32_t)((rA + 16) * 128 + ks * 32 + kbA)));
            uint32_t b[8][2];
            #pragma unroll
            for (int g = 0; g < 4; g++) {
                uint32_t t[4];
                ldsm_x4(t, bT + SWZ((uint32_t)((rB + g * 16) * 128 + ks * 32 + kbB)));
                b[2 * g][0]     = t[0]; b[2 * g][1]     = t[1];
                b[2 * g + 1][0] = t[2]; b[2 * g + 1][1] = t[3];
            }
            #pragma unroll
            for (int mm = 0; mm < 2; mm++)
                #pragma unroll
                for (int nt = 0; nt < 8; nt++)
                    mma16816(acc[mm][nt], a[mm], b[nt]);
        }
        // no trailing barrier: stage (kt+2)%3 was last read at iteration kt-1,
        // strictly before the barrier at iteration kt that precedes its refill.
    }

    // Epilogue: convert to fp16, coalesced half2 stores
    const int gid = lane >> 2, tig = lane & 3;
    #pragma unroll
    for (int mm = 0; mm < 2; mm++) {
        const long mrow = (long)(m0 + warp_m * 32 + mm * 16 + gid);
        __half* base0 = g_P + mrow * NPAD + n0 + warp_n * 64 + tig * 2;
        __half* base1 = base0 + 8L * NPAD;
        #pragma unroll
        for (int nt = 0; nt < 8; nt++) {
            *(__half2*)(base0 + nt * 8) =
                __floats2half2_rn(acc[mm][nt][0], acc[mm][nt][1]);
            *(__half2*)(base1 + nt * 8) =
                __floats2half2_rn(acc[mm][nt][2], acc[mm][nt][3]);
        }
    }
}

// ============================================================================
// Fusion kernel: one warp per token, fully half2/float2 vectorized
//   P row layout (half2 units): [q(384) | k(384) | v(384) | h_s(96) | h_o(96)]
// ============================================================================
__global__ void __launch_bounds__(256) fusion_kernel(
    const float* __restrict__ x1, const float* __restrict__ x2,
    const float* __restrict__ b1, const float* __restrict__ W2,
    const float* __restrict__ b2, float* __restrict__ out) {
    const int token = blockIdx.x * 8 + (threadIdx.x >> 5);
    const int lane = threadIdx.x & 31;
    const long r  = token;
    const long ro = (r < MTOT / 2) ? (r + MTOT / 2) : (r - MTOT / 2);
    const __half2* Pr = (const __half2*)g_P + r * (NPAD / 2);
    const __half2* Po = (const __half2*)g_P + ro * (NPAD / 2);

    float ds = 0.0f, dc = 0.0f;
    #pragma unroll
    for (int i = 0; i < 12; i++) {
        int d2 = lane + i * 32;                    // half2 index 0..383
        float2 q  = __half22float2(Pr[d2]);
        float2 ks = __half22float2(Pr[384 + d2]);
        float2 kc = __half22float2(Po[384 + d2]);
        float2 nk = *(const float2*)(g_nk + 2 * d2);
        ds += q.x * (ks.x + nk.x) + q.y * (ks.y + nk.y);
        dc += q.x * kc.x + q.y * kc.y;
    }
    float hacc = 0.0f;
    #pragma unroll
    for (int i = 0; i < 3; i++) {
        int j2 = lane + i * 32;                    // half2 index 0..95
        float2 hs = __half22float2(Pr[1152 + j2]);
        float2 ho = __half22float2(Po[1248 + j2]);
        float2 bb = *(const float2*)(b1 + 2 * j2);
        float2 ww = *(const float2*)(W2 + 2 * j2);
        float h0 = hs.x + ho.x + bb.x;
        float h1 = hs.y + ho.y + bb.y;
        h0 = 0.5f * h0 * (1.0f + erff(h0 * 0.7071067811865476f));
        h1 = 0.5f * h1 * (1.0f + erff(h1 * 0.7071067811865476f));
        hacc += h0 * ww.x + h1 * ww.y;
    }
    #pragma unroll
    for (int o = 16; o; o >>= 1) {
        ds   += __shfl_xor_sync(0xFFFFFFFFu, ds, o);
        dc   += __shfl_xor_sync(0xFFFFFFFFu, dc, o);
        hacc += __shfl_xor_sync(0xFFFFFFFFu, hacc, o);
    }
    const float rel = 1.0f / (1.0f + expf(-(hacc + b2[0])));
    const float SCALE = 0.03608439182435161f;  // 768^-0.5
    float d0 = ds * SCALE;
    float d1 = dc * rel * SCALE;
    float mx = fmaxf(d0, d1);
    float e0 = expf(d0 - mx), e1 = expf(d1 - mx);
    float inv = 1.0f / (e0 + e1);
    float w0 = e0 * inv, w1 = e1 * inv;

    const float* xsrc = (r < MTOT / 2) ? (x1 + r * DIM)
                                       : (x2 + (r - MTOT / 2) * DIM);
    float* orow = out + r * DIM;
    #pragma unroll
    for (int i = 0; i < 12; i++) {
        int d2 = lane + i * 32;
        float2 vs = __half22float2(Pr[768 + d2]);
        float2 vc = __half22float2(Po[768 + d2]);
        float2 xs = *(const float2*)(xsrc + 2 * d2);
        float2 o;
        o.x = xs.x + w0 * vs.x + w1 * vc.x;
        o.y = xs.y + w0 * vs.y + w1 * vc.y;
        *(float2*)(orow + 2 * d2) = o;
    }
}

// ============================================================================
// Launch
// ============================================================================
extern "C" void kernel_launch(void* const* d_in, const int* in_sizes, int n_in,
                              void* d_out, int out_size) {
    const float* x1    = (const float*)d_in[0];
    const float* x2    = (const float*)d_in[1];
    const float* Wq    = (const float*)d_in[2];
    const float* Wk    = (const float*)d_in[3];
    const float* Wv    = (const float*)d_in[4];
    const float* noise = (const float*)d_in[5];
    const float* W1    = (const float*)d_in[6];
    const float* b1    = (const float*)d_in[7];
    const float* W2    = (const float*)d_in[8];
    const float* b2    = (const float*)d_in[9];
    float* out = (float*)d_out;

    cudaFuncSetAttribute(gemm_kernel,
                         cudaFuncAttributeMaxDynamicSharedMemorySize, SM_TOTAL);

    prep_w_kernel<<<NPAD, 256>>>(Wq, Wk, Wv, W1);
    prep_x_kernel<<<MTOT, 256>>>(x1, x2);
    nk_kernel<<<6, 128>>>(noise, Wk);

    dim3 grid(NPAD / BN, MTOT / BM);   // (21, 512)
    gemm_kernel<<<grid, 256, SM_TOTAL>>>();

    fusion_kernel<<<MTOT / 8, 256>>>(x1, x2, b1, W2, b2, out);
}

// round 7
// speedup vs baseline: 2.4350x; 1.1027x over previous
#include <cuda_runtime.h>
#include <cuda_fp16.h>
#include <cstdint>
#include <math.h>

// ============================================================================
// Problem constants
//   x1,x2: [32,1024,768]  -> stacked X: [65536, 768]
//   M = Wq @ Wk^T  (768x768, tiny GEMM).   c = Wq @ (noise@Wk).
//   P = X @ [M | Wv | W1a | W1b] : [65536, 1920]   (m | v | h_a | h_b)
//   d_self  = m.x + c.x ;  d_cross = m.x_other  (bilinear-form folding)
//   fp16 GEMM (K=768), P stored fp16.
// ============================================================================
#define MTOT   65536
#define DIM    768
#define NPAD   1920            // 15 * 128: m(768) | v(768) | h_a(192) | h_b(192)
#define KPA    768
#define KPB    768
#define KEFF   768

#define BM 128
#define BN 128
#define BK 64
#define KT (KEFF / BK)         // 12
#define STAGES 3

// ============================================================================
// Scratch (__device__ globals)
// ============================================================================
__device__ __half g_Xc  [(long)MTOT * KPA];   // [65536][768] fp16
__device__ __half g_Wc  [(long)NPAD * KPB];   // [1920][768]  fp16, n-major
__device__ __half g_P   [(long)MTOT * NPAD];  // [65536][1920] fp16
__device__ __half g_Wq16[(long)DIM * DIM];    // fp16 copy of Wq (row-major in,out)
__device__ __half g_Wk16[(long)DIM * DIM];    // fp16 copy of Wk
__device__ float  g_nk[DIM];                  // noise @ Wk
__device__ float  g_c [DIM];                  // Wq @ nk

// ============================================================================
// Helpers
// ============================================================================
__device__ __forceinline__ uint32_t smem_to_u32(const void* smem_ptr) {
    uint32_t addr;
    asm("{ .reg .u64 tmp; cvta.to.shared.u64 tmp, %1; cvt.u32.u64 %0, tmp; }"
        : "=r"(addr) : "l"(smem_ptr));
    return addr;
}

#define SWZ(byte_offset) ((byte_offset) ^ ((((uint32_t)(byte_offset)) >> 3) & 0x70))

__device__ __forceinline__ void cp_async16(uint32_t dst_smem, const void* src) {
    asm volatile("cp.async.cg.shared.global [%0], [%1], 16;"
        :: "r"(dst_smem), "l"(src) : "memory");
}
#define CP_ASYNC_COMMIT()  asm volatile("cp.async.commit_group;" ::: "memory")
#define CP_ASYNC_WAIT(N)   asm volatile("cp.async.wait_group %0;" :: "n"(N) : "memory")

__device__ __forceinline__ void ldsm_x4(uint32_t* r, uint32_t addr) {
    asm volatile("ldmatrix.sync.aligned.m8n8.x4.shared.b16 {%0,%1,%2,%3}, [%4];"
        : "=r"(r[0]), "=r"(r[1]), "=r"(r[2]), "=r"(r[3]) : "r"(addr));
}

__device__ __forceinline__ void mma16816(float* c, const uint32_t* a, const uint32_t* b) {
    asm volatile(
        "mma.sync.aligned.m16n8k16.row.col.f32.f16.f16.f32 "
        "{%0,%1,%2,%3}, {%4,%5,%6,%7}, {%8,%9}, {%0,%1,%2,%3};"
        : "+f"(c[0]), "+f"(c[1]), "+f"(c[2]), "+f"(c[3])
        : "r"(a[0]), "r"(a[1]), "r"(a[2]), "r"(a[3]), "r"(b[0]), "r"(b[1]));
}

// ============================================================================
// Prep kernels
// ============================================================================
__global__ void prep_x_kernel(const float* __restrict__ x1,
                              const float* __restrict__ x2) {
    long r = blockIdx.x;
    const float* src = (r < (MTOT / 2)) ? (x1 + r * DIM)
                                        : (x2 + (r - MTOT / 2) * DIM);
    __half* dst = g_Xc + r * KPA;
    for (int c = threadIdx.x; c < DIM; c += blockDim.x)
        dst[c] = __float2half(src[c]);
}

// fp16 copies of Wq, Wk (row-major (in,out), K-contiguous per row)
__global__ void prep_qk_kernel(const float* __restrict__ Wq,
                               const float* __restrict__ Wk) {
    long i = blockIdx.x;
    for (int e = threadIdx.x; e < DIM; e += blockDim.x) {
        g_Wq16[i * DIM + e] = __float2half(Wq[i * DIM + e]);
        g_Wk16[i * DIM + e] = __float2half(Wk[i * DIM + e]);
    }
}

// fills g_Wc rows [768, 1920): Wv | W1a | W1b   (rows [0,768) come from M-gemm)
__global__ void prep_w_kernel(const float* __restrict__ Wv,
                              const float* __restrict__ W1) {
    int n = blockIdx.x + 768;  // 768..1919
    __half* dst = g_Wc + (long)n * KPB;
    for (int j = threadIdx.x; j < DIM; j += blockDim.x) {
        float w;
        if      (n < 1536) w = Wv[j * 768 + (n - 768)];
        else if (n < 1728) w = W1[j * 192 + (n - 1536)];          // W1a (rows 0..767)
        else               w = W1[(768 + j) * 192 + (n - 1728)];  // W1b (rows 768..1535)
        dst[j] = __float2half(w);
    }
}

__global__ void nk_kernel(const float* __restrict__ noise,
                          const float* __restrict__ Wk) {
    int d = blockIdx.x * blockDim.x + threadIdx.x;
    if (d >= DIM) return;
    float acc = 0.0f;
    for (int j = 0; j < DIM; j++) acc += noise[j] * Wk[j * 768 + d];
    g_nk[d] = acc;
}

__global__ void c_kernel(const float* __restrict__ Wq) {
    int d = blockIdx.x * blockDim.x + threadIdx.x;
    if (d >= DIM) return;
    float acc = 0.0f;
    for (int e = 0; e < DIM; e++) acc += Wq[d * 768 + e] * g_nk[e];
    g_c[d] = acc;
}

// ============================================================================
// Generic fp16 GEMM: C[mrow][n] = sum_k A[mrow][k] * B[n][k], K=768.
// mma.sync.m16n8k16. 256 threads, 8 warps (4 m x 2 n), BM=BN=128, BK=64.
// Used for the main P-GEMM (C=g_P, ldc=1920) and the tiny M-GEMM
// (A=Wk16, B=Wq16, C=g_Wc rows 0..767, ldc=768:  C[j][i] = sum_e Wk[j,e]Wq[i,e]).
// ============================================================================
#define STAGE_BYTES 32768
#define SM_TOTAL    (STAGES * STAGE_BYTES)

__global__ void __launch_bounds__(256, 2)
hgemm_kernel(const __half* __restrict__ A, const __half* __restrict__ B,
             __half* __restrict__ C, int ldc) {
    extern __shared__ char smem[];
    const uint32_t sbase = smem_to_u32(smem);
    const int tid    = threadIdx.x;
    const int wid    = tid >> 5;
    const int lane   = tid & 31;
    const int warp_m = wid & 3;   // 0..3, 32 rows each
    const int warp_n = wid >> 2;  // 0..1, 64 cols each
    const int m0 = blockIdx.y * BM;
    const int n0 = blockIdx.x * BN;

    const __half* Ag = A + (long)m0 * KPA;
    const __half* Bg = B + (long)n0 * KPB;

    auto load_stage = [&](int kt, int st) {
        const int k0 = kt * BK;
        const uint32_t aT = sbase + st * STAGE_BYTES;
        const uint32_t bT = aT + 16384;
        #pragma unroll
        for (int i = 0; i < 4; i++) {
            int idx = tid + i * 256;
            int row = idx >> 3, c = idx & 7;
            cp_async16(aT + SWZ((uint32_t)(row * 128 + c * 16)),
                       (const char*)(Ag + (long)row * KPA + k0) + c * 16);
        }
        #pragma unroll
        for (int i = 0; i < 4; i++) {
            int idx = tid + i * 256;
            int row = idx >> 3, c = idx & 7;
            cp_async16(bT + SWZ((uint32_t)(row * 128 + c * 16)),
                       (const char*)(Bg + (long)row * KPB + k0) + c * 16);
        }
        CP_ASYNC_COMMIT();
    };

    float acc[2][8][4];
    #pragma unroll
    for (int mm = 0; mm < 2; mm++)
        #pragma unroll
        for (int nt = 0; nt < 8; nt++)
            #pragma unroll
            for (int q = 0; q < 4; q++) acc[mm][nt][q] = 0.0f;

    load_stage(0, 0);
    load_stage(1, 1);

    // ldmatrix lane->address precomputation
    const int rA  = warp_m * 32 + (lane & 7) + ((lane >> 3) & 1) * 8;
    const int kbA = ((lane >> 4) & 1) * 16;
    const int rB  = warp_n * 64 + (lane & 7) + ((lane >> 4) & 1) * 8;
    const int kbB = ((lane >> 3) & 1) * 16;

    for (int kt = 0; kt < KT; kt++) {
        if (kt + 1 < KT) { CP_ASYNC_WAIT(1); } else { CP_ASYNC_WAIT(0); }
        __syncthreads();
        if (kt + 2 < KT) load_stage(kt + 2, (kt + 2) % STAGES);

        const uint32_t aT = sbase + (kt % STAGES) * STAGE_BYTES;
        const uint32_t bT = aT + 16384;

        #pragma unroll
        for (int ks = 0; ks < 4; ks++) {
            uint32_t a[2][4];
            ldsm_x4(a[0], aT + SWZ((uint32_t)(rA * 128 + ks * 32 + kbA)));
            ldsm_x4(a[1], aT + SWZ((uint32_t)((rA + 16) * 128 + ks * 32 + kbA)));
            uint32_t b[8][2];
            #pragma unroll
            for (int g = 0; g < 4; g++) {
                uint32_t t[4];
                ldsm_x4(t, bT + SWZ((uint32_t)((rB + g * 16) * 128 + ks * 32 + kbB)));
                b[2 * g][0]     = t[0]; b[2 * g][1]     = t[1];
                b[2 * g + 1][0] = t[2]; b[2 * g + 1][1] = t[3];
            }
            #pragma unroll
            for (int mm = 0; mm < 2; mm++)
                #pragma unroll
                for (int nt = 0; nt < 8; nt++)
                    mma16816(acc[mm][nt], a[mm], b[nt]);
        }
        // no trailing barrier: stage (kt+2)%3 was last read at iteration kt-1,
        // strictly before the barrier at iteration kt that precedes its refill.
    }

    // Epilogue: convert to fp16, coalesced half2 stores
    const int gid = lane >> 2, tig = lane & 3;
    #pragma unroll
    for (int mm = 0; mm < 2; mm++) {
        const long mrow = (long)(m0 + warp_m * 32 + mm * 16 + gid);
        __half* base0 = C + mrow * ldc + n0 + warp_n * 64 + tig * 2;
        __half* base1 = base0 + 8L * ldc;
        #pragma unroll
        for (int nt = 0; nt < 8; nt++) {
            *(__half2*)(base0 + nt * 8) =
                __floats2half2_rn(acc[mm][nt][0], acc[mm][nt][1]);
            *(__half2*)(base1 + nt * 8) =
                __floats2half2_rn(acc[mm][nt][2], acc[mm][nt][3]);
        }
    }
}

// ============================================================================
// Fusion kernel: one warp per token, fully half2/float2 vectorized
//   P row layout (half2 units): [m(384) | v(384) | h_a(96) | h_b(96)]
//   d_self  = (m_r + c) . x_r      d_cross = m_r . x_ro
// ============================================================================
__global__ void __launch_bounds__(256) fusion_kernel(
    const float* __restrict__ x1, const float* __restrict__ x2,
    const float* __restrict__ b1, const float* __restrict__ W2,
    const float* __restrict__ b2, float* __restrict__ out) {
    const int token = blockIdx.x * 8 + (threadIdx.x >> 5);
    const int lane = threadIdx.x & 31;
    const long r  = token;
    const long ro = (r < MTOT / 2) ? (r + MTOT / 2) : (r - MTOT / 2);
    const __half2* Pr = (const __half2*)g_P + r * (NPAD / 2);
    const __half2* Po = (const __half2*)g_P + ro * (NPAD / 2);

    const float* xsrc = (r < MTOT / 2) ? (x1 + r * DIM)
                                       : (x2 + (r - MTOT / 2) * DIM);
    const float* xoth = (ro < MTOT / 2) ? (x1 + ro * DIM)
                                        : (x2 + (ro - MTOT / 2) * DIM);

    float ds = 0.0f, dc = 0.0f;
    float2 xsv[12];
    #pragma unroll
    for (int i = 0; i < 12; i++) {
        int d2 = lane + i * 32;                    // half2 index 0..383
        float2 m  = __half22float2(Pr[d2]);
        float2 xs = *(const float2*)(xsrc + 2 * d2);
        float2 xo = *(const float2*)(xoth + 2 * d2);
        float2 cc = *(const float2*)(g_c + 2 * d2);
        xsv[i] = xs;
        ds += (m.x + cc.x) * xs.x + (m.y + cc.y) * xs.y;
        dc += m.x * xo.x + m.y * xo.y;
    }
    float hacc = 0.0f;
    #pragma unroll
    for (int i = 0; i < 3; i++) {
        int j2 = lane + i * 32;                    // half2 index 0..95
        float2 hs = __half22float2(Pr[768 + j2]);  // h_a of self
        float2 ho = __half22float2(Po[864 + j2]);  // h_b of other
        float2 bb = *(const float2*)(b1 + 2 * j2);
        float2 ww = *(const float2*)(W2 + 2 * j2);
        float h0 = hs.x + ho.x + bb.x;
        float h1 = hs.y + ho.y + bb.y;
        h0 = 0.5f * h0 * (1.0f + erff(h0 * 0.7071067811865476f));
        h1 = 0.5f * h1 * (1.0f + erff(h1 * 0.7071067811865476f));
        hacc += h0 * ww.x + h1 * ww.y;
    }
    #pragma unroll
    for (int o = 16; o; o >>= 1) {
        ds   += __shfl_xor_sync(0xFFFFFFFFu, ds, o);
        dc   += __shfl_xor_sync(0xFFFFFFFFu, dc, o);
        hacc += __shfl_xor_sync(0xFFFFFFFFu, hacc, o);
    }
    const float rel = 1.0f / (1.0f + expf(-(hacc + b2[0])));
    const float SCALE = 0.03608439182435161f;  // 768^-0.5
    float d0 = ds * SCALE;
    float d1 = dc * rel * SCALE;
    float mx = fmaxf(d0, d1);
    float e0 = expf(d0 - mx), e1 = expf(d1 - mx);
    float inv = 1.0f / (e0 + e1);
    float w0 = e0 * inv, w1 = e1 * inv;

    float* orow = out + r * DIM;
    #pragma unroll
    for (int i = 0; i < 12; i++) {
        int d2 = lane + i * 32;
        float2 vs = __half22float2(Pr[384 + d2]);
        float2 vc = __half22float2(Po[384 + d2]);
        float2 o;
        o.x = xsv[i].x + w0 * vs.x + w1 * vc.x;
        o.y = xsv[i].y + w0 * vs.y + w1 * vc.y;
        *(float2*)(orow + 2 * d2) = o;
    }
}

// ============================================================================
// Launch
// ============================================================================
extern "C" void kernel_launch(void* const* d_in, const int* in_sizes, int n_in,
                              void* d_out, int out_size) {
    const float* x1    = (const float*)d_in[0];
    const float* x2    = (const float*)d_in[1];
    const float* Wq    = (const float*)d_in[2];
    const float* Wk    = (const float*)d_in[3];
    const float* Wv    = (const float*)d_in[4];
    const float* noise = (const float*)d_in[5];
    const float* W1    = (const float*)d_in[6];
    const float* b1    = (const float*)d_in[7];
    const float* W2    = (const float*)d_in[8];
    const float* b2    = (const float*)d_in[9];
    float* out = (float*)d_out;

    cudaFuncSetAttribute(hgemm_kernel,
                         cudaFuncAttributeMaxDynamicSharedMemorySize, SM_TOTAL);

    // device pointers to __device__ globals (host-side symbol addresses)
    __half *pXc, *pWc, *pP, *pWq16, *pWk16;
    cudaGetSymbolAddress((void**)&pXc,   g_Xc);
    cudaGetSymbolAddress((void**)&pWc,   g_Wc);
    cudaGetSymbolAddress((void**)&pP,    g_P);
    cudaGetSymbolAddress((void**)&pWq16, g_Wq16);
    cudaGetSymbolAddress((void**)&pWk16, g_Wk16);

    prep_qk_kernel<<<DIM, 256>>>(Wq, Wk);
    prep_w_kernel<<<NPAD - 768, 256>>>(Wv, W1);
    prep_x_kernel<<<MTOT, 256>>>(x1, x2);
    nk_kernel<<<6, 128>>>(noise, Wk);
    c_kernel<<<6, 128>>>(Wq);

    // M-GEMM: g_Wc[j][i] = sum_e Wk[j,e] * Wq[i,e]   (rows 0..767 of g_Wc)
    {
        dim3 grid(DIM / BN, DIM / BM);  // (6, 6)
        hgemm_kernel<<<grid, 256, SM_TOTAL>>>(pWk16, pWq16, pWc, KPB);
    }

    // Main GEMM: P = X @ [M | Wv | W1a | W1b]
    {
        dim3 grid(NPAD / BN, MTOT / BM);  // (15, 512)
        hgemm_kernel<<<grid, 256, SM_TOTAL>>>(pXc, pWc, pP, NPAD);
    }

    fusion_kernel<<<MTOT / 8, 256>>>(x1, x2, b1, W2, b2, out);
}

// round 8
// speedup vs baseline: 2.5900x; 1.0636x over previous
#include <cuda_runtime.h>
#include <cuda_fp16.h>
#include <cstdint>
#include <math.h>

// ============================================================================
//   M = Wq @ Wk^T (768x768).   c = Wq @ (noise@Wk).
//   P = X @ [M | Wv | W1a | W1b] : [65536, 1920]  (m | v | h_a | h_b)
//   d_self = (m + c).x ;  d_cross = m.x_other
// ============================================================================
#define MTOT   65536
#define HALFM  32768
#define DIM    768
#define NPAD   1920
#define KPA    768
#define KPB    768
#define KEFF   768

#define BM 256
#define BN 128
#define BK 64
#define KT (KEFF / BK)         // 12
#define STAGES 4
#define A_STAGE 32768          // 256 rows x 128 B
#define B_STAGE 16384          // 128 rows x 128 B
#define STAGE_BYTES (A_STAGE + B_STAGE)
#define SM_TOTAL (STAGES * STAGE_BYTES)   // 192 KB

// ============================================================================
// Scratch
// ============================================================================
__device__ __half g_Xc  [(long)MTOT * KPA];
__device__ __half g_Wc  [(long)NPAD * KPB];
__device__ __half g_P   [(long)MTOT * NPAD];
__device__ __half g_Wq16[(long)DIM * DIM];
__device__ __half g_Wk16[(long)DIM * DIM];
__device__ float  g_nk[DIM];
__device__ float  g_c [DIM];

// ============================================================================
// Helpers
// ============================================================================
__device__ __forceinline__ uint32_t smem_to_u32(const void* smem_ptr) {
    uint32_t addr;
    asm("{ .reg .u64 tmp; cvta.to.shared.u64 tmp, %1; cvt.u32.u64 %0, tmp; }"
        : "=r"(addr) : "l"(smem_ptr));
    return addr;
}

#define SWZ(byte_offset) ((byte_offset) ^ ((((uint32_t)(byte_offset)) >> 3) & 0x70))

__device__ __forceinline__ void cp_async16(uint32_t dst_smem, const void* src) {
    asm volatile("cp.async.cg.shared.global [%0], [%1], 16;"
        :: "r"(dst_smem), "l"(src) : "memory");
}
#define CP_ASYNC_COMMIT()  asm volatile("cp.async.commit_group;" ::: "memory")
#define CP_ASYNC_WAIT(N)   asm volatile("cp.async.wait_group %0;" :: "n"(N) : "memory")

__device__ __forceinline__ void ldsm_x4(uint32_t* r, uint32_t addr) {
    asm volatile("ldmatrix.sync.aligned.m8n8.x4.shared.b16 {%0,%1,%2,%3}, [%4];"
        : "=r"(r[0]), "=r"(r[1]), "=r"(r[2]), "=r"(r[3]) : "r"(addr));
}

__device__ __forceinline__ void mma16816(float* c, const uint32_t* a, const uint32_t* b) {
    asm volatile(
        "mma.sync.aligned.m16n8k16.row.col.f32.f16.f16.f32 "
        "{%0,%1,%2,%3}, {%4,%5,%6,%7}, {%8,%9}, {%0,%1,%2,%3};"
        : "+f"(c[0]), "+f"(c[1]), "+f"(c[2]), "+f"(c[3])
        : "r"(a[0]), "r"(a[1]), "r"(a[2]), "r"(a[3]), "r"(b[0]), "r"(b[1]));
}

// ============================================================================
// Prep kernels
// ============================================================================
__global__ void prep_x_kernel(const float* __restrict__ x1,
                              const float* __restrict__ x2) {
    long r = blockIdx.x;
    const float* src = (r < HALFM) ? (x1 + r * DIM) : (x2 + (r - HALFM) * DIM);
    __half* dst = g_Xc + r * KPA;
    for (int c = threadIdx.x; c < DIM; c += blockDim.x)
        dst[c] = __float2half(src[c]);
}

__global__ void prep_qk_kernel(const float* __restrict__ Wq,
                               const float* __restrict__ Wk) {
    long i = blockIdx.x;
    for (int e = threadIdx.x; e < DIM; e += blockDim.x) {
        g_Wq16[i * DIM + e] = __float2half(Wq[i * DIM + e]);
        g_Wk16[i * DIM + e] = __float2half(Wk[i * DIM + e]);
    }
}

__global__ void prep_w_kernel(const float* __restrict__ Wv,
                              const float* __restrict__ W1) {
    int n = blockIdx.x + 768;  // 768..1919
    __half* dst = g_Wc + (long)n * KPB;
    for (int j = threadIdx.x; j < DIM; j += blockDim.x) {
        float w;
        if      (n < 1536) w = Wv[j * 768 + (n - 768)];
        else if (n < 1728) w = W1[j * 192 + (n - 1536)];
        else               w = W1[(768 + j) * 192 + (n - 1728)];
        dst[j] = __float2half(w);
    }
}

__global__ void zero_nk_kernel() {
    if (threadIdx.x < DIM) g_nk[threadIdx.x] = 0.0f;
}

// nk[d] = sum_j noise[j] * Wk[j*768+d]; j split over blockIdx.y (coalesced in d)
__global__ void nk_partial_kernel(const float* __restrict__ noise,
                                  const float* __restrict__ Wk) {
    const int d  = blockIdx.x * 128 + threadIdx.x;
    const int j0 = blockIdx.y * 48;
    float acc = 0.0f;
    #pragma unroll
    for (int j = 0; j < 48; j++)
        acc += noise[j0 + j] * Wk[(long)(j0 + j) * 768 + d];
    atomicAdd(&g_nk[d], acc);
}

// c[d] = Wq[d,:] . nk  — one warp per d, lane-strided coalesced reads
__global__ void c_kernel(const float* __restrict__ Wq) {
    const int wid  = threadIdx.x >> 5;
    const int lane = threadIdx.x & 31;
    const int d    = blockIdx.x * 8 + wid;
    float acc = 0.0f;
    #pragma unroll
    for (int i = 0; i < 24; i++) {
        int e = lane + i * 32;
        acc += Wq[(long)d * 768 + e] * g_nk[e];
    }
    #pragma unroll
    for (int o = 16; o; o >>= 1) acc += __shfl_xor_sync(0xFFFFFFFFu, acc, o);
    if (lane == 0) g_c[d] = acc;
}

// ============================================================================
// fp16 GEMM: C[m][n] = sum_k A[m][k]*B[n][k], K=768.  BM=256, BN=128, BK=64.
// 8 warps (4 m x 2 n), 64x64 warp tiles, 4-stage cp.async, 1 CTA/SM.
// ============================================================================
__global__ void __launch_bounds__(256, 1)
hgemm_kernel(const __half* __restrict__ A, const __half* __restrict__ B,
             __half* __restrict__ C, int ldc) {
    extern __shared__ char smem[];
    const uint32_t sbase = smem_to_u32(smem);
    const int tid    = threadIdx.x;
    const int wid    = tid >> 5;
    const int lane   = tid & 31;
    const int warp_m = wid >> 1;  // 0..3, 64 rows each
    const int warp_n = wid & 1;   // 0..1, 64 cols each
    const int m0 = blockIdx.y * BM;
    const int n0 = blockIdx.x * BN;

    const __half* Ag = A + (long)m0 * KPA;
    const __half* Bg = B + (long)n0 * KPB;

    auto load_stage = [&](int kt, int st) {
        const int k0 = kt * BK;
        const uint32_t aT = sbase + st * STAGE_BYTES;
        const uint32_t bT = aT + A_STAGE;
        #pragma unroll
        for (int i = 0; i < 8; i++) {           // A: 256 rows x 8 chunks
            int idx = tid + i * 256;
            int row = idx >> 3, c = idx & 7;
            cp_async16(aT + SWZ((uint32_t)(row * 128 + c * 16)),
                       (const char*)(Ag + (long)row * KPA + k0) + c * 16);
        }
        #pragma unroll
        for (int i = 0; i < 4; i++) {           // B: 128 rows x 8 chunks
            int idx = tid + i * 256;
            int row = idx >> 3, c = idx & 7;
            cp_async16(bT + SWZ((uint32_t)(row * 128 + c * 16)),
                       (const char*)(Bg + (long)row * KPB + k0) + c * 16);
        }
        CP_ASYNC_COMMIT();
    };

    float acc[4][8][4];
    #pragma unroll
    for (int mm = 0; mm < 4; mm++)
        #pragma unroll
        for (int nt = 0; nt < 8; nt++)
            #pragma unroll
            for (int q = 0; q < 4; q++) acc[mm][nt][q] = 0.0f;

    load_stage(0, 0);
    load_stage(1, 1);
    load_stage(2, 2);

    const int rA  = warp_m * 64 + (lane & 7) + ((lane >> 3) & 1) * 8;
    const int kbA = ((lane >> 4) & 1) * 16;
    const int rB  = warp_n * 64 + (lane & 7) + ((lane >> 4) & 1) * 8;
    const int kbB = ((lane >> 3) & 1) * 16;

    for (int kt = 0; kt < KT; kt++) {
        if (kt + 1 < KT) { CP_ASYNC_WAIT(2); } else { CP_ASYNC_WAIT(0); }
        __syncthreads();
        if (kt + 3 < KT) load_stage(kt + 3, (kt + 3) % STAGES);

        const uint32_t aT = sbase + (kt % STAGES) * STAGE_BYTES;
        const uint32_t bT = aT + A_STAGE;

        #pragma unroll
        for (int ks = 0; ks < 4; ks++) {
            uint32_t a[4][4];
            #pragma unroll
            for (int mm = 0; mm < 4; mm++)
                ldsm_x4(a[mm], aT + SWZ((uint32_t)((rA + mm * 16) * 128 +
                                                   ks * 32 + kbA)));
            #pragma unroll
            for (int g = 0; g < 4; g++) {
                uint32_t t[4];
                ldsm_x4(t, bT + SWZ((uint32_t)((rB + g * 16) * 128 +
                                               ks * 32 + kbB)));
                #pragma unroll
                for (int mm = 0; mm < 4; mm++) {
                    mma16816(acc[mm][2 * g],     a[mm], t);
                    mma16816(acc[mm][2 * g + 1], a[mm], t + 2);
                }
            }
        }
        // single barrier per k-tile: stage (kt+3)%4 was last read at kt-1,
        // strictly before this iteration's barrier.
    }

    // Epilogue: fp16 half2 stores
    const int gid = lane >> 2, tig = lane & 3;
    #pragma unroll
    for (int mm = 0; mm < 4; mm++) {
        const long mrow = (long)(m0 + warp_m * 64 + mm * 16 + gid);
        __half* base0 = C + mrow * ldc + n0 + warp_n * 64 + tig * 2;
        __half* base1 = base0 + 8L * ldc;
        #pragma unroll
        for (int nt = 0; nt < 8; nt++) {
            *(__half2*)(base0 + nt * 8) =
                __floats2half2_rn(acc[mm][nt][0], acc[mm][nt][1]);
            *(__half2*)(base1 + nt * 8) =
                __floats2half2_rn(acc[mm][nt][2], acc[mm][nt][3]);
        }
    }
}

// ============================================================================
// Fusion: one warp per token PAIR (r, r+32768); m and x read once per pair.
//   P row layout (half2 units): [m(384) | v(384) | h_a(96) | h_b(96)]
// ============================================================================
__global__ void __launch_bounds__(256) fusion_kernel(
    const float* __restrict__ x1, const float* __restrict__ x2,
    const float* __restrict__ b1, const float* __restrict__ W2,
    const float* __restrict__ b2, float* __restrict__ out) {
    const int t   = blockIdx.x * 8 + (threadIdx.x >> 5);  // pair id 0..32767
    const int lane = threadIdx.x & 31;
    const __half2* Pr = (const __half2*)g_P + (long)t * (NPAD / 2);
    const __half2* Po = (const __half2*)g_P + (long)(t + HALFM) * (NPAD / 2);
    const float* xr = x1 + (long)t * DIM;
    const float* xo = x2 + (long)t * DIM;

    float ds_r = 0.0f, dc_r = 0.0f, ds_o = 0.0f, dc_o = 0.0f;
    float2 xrv[12], xov[12];
    #pragma unroll
    for (int i = 0; i < 12; i++) {
        int d2 = lane + i * 32;
        float2 mr = __half22float2(Pr[d2]);
        float2 mo = __half22float2(Po[d2]);
        float2 xs = *(const float2*)(xr + 2 * d2);
        float2 xq = *(const float2*)(xo + 2 * d2);
        float2 cc = *(const float2*)(g_c + 2 * d2);
        xrv[i] = xs; xov[i] = xq;
        ds_r += (mr.x + cc.x) * xs.x + (mr.y + cc.y) * xs.y;
        dc_r += mr.x * xq.x + mr.y * xq.y;
        ds_o += (mo.x + cc.x) * xq.x + (mo.y + cc.y) * xq.y;
        dc_o += mo.x * xs.x + mo.y * xs.y;
    }
    float ha_r = 0.0f, ha_o = 0.0f;
    #pragma unroll
    for (int i = 0; i < 3; i++) {
        int j2 = lane + i * 32;
        float2 ar = __half22float2(Pr[768 + j2]);   // h_a(r)
        float2 br = __half22float2(Pr[864 + j2]);   // h_b(r)
        float2 ao = __half22float2(Po[768 + j2]);   // h_a(o)
        float2 bo = __half22float2(Po[864 + j2]);   // h_b(o)
        float2 bb = *(const float2*)(b1 + 2 * j2);
        float2 ww = *(const float2*)(W2 + 2 * j2);
        float r0 = ar.x + bo.x + bb.x, r1 = ar.y + bo.y + bb.y;
        float o0 = ao.x + br.x + bb.x, o1 = ao.y + br.y + bb.y;
        r0 = 0.5f * r0 * (1.0f + erff(r0 * 0.7071067811865476f));
        r1 = 0.5f * r1 * (1.0f + erff(r1 * 0.7071067811865476f));
        o0 = 0.5f * o0 * (1.0f + erff(o0 * 0.7071067811865476f));
        o1 = 0.5f * o1 * (1.0f + erff(o1 * 0.7071067811865476f));
        ha_r += r0 * ww.x + r1 * ww.y;
        ha_o += o0 * ww.x + o1 * ww.y;
    }
    #pragma unroll
    for (int o = 16; o; o >>= 1) {
        ds_r += __shfl_xor_sync(0xFFFFFFFFu, ds_r, o);
        dc_r += __shfl_xor_sync(0xFFFFFFFFu, dc_r, o);
        ds_o += __shfl_xor_sync(0xFFFFFFFFu, ds_o, o);
        dc_o += __shfl_xor_sync(0xFFFFFFFFu, dc_o, o);
        ha_r += __shfl_xor_sync(0xFFFFFFFFu, ha_r, o);
        ha_o += __shfl_xor_sync(0xFFFFFFFFu, ha_o, o);
    }
    const float bias = b2[0];
    const float SCALE = 0.03608439182435161f;  // 768^-0.5
    float rel_r = 1.0f / (1.0f + expf(-(ha_r + bias)));
    float rel_o = 1.0f / (1.0f + expf(-(ha_o + bias)));
    float d0r = ds_r * SCALE, d1r = dc_r * rel_r * SCALE;
    float d0o = ds_o * SCALE, d1o = dc_o * rel_o * SCALE;
    float mr = fmaxf(d0r, d1r), mo = fmaxf(d0o, d1o);
    float e0r = expf(d0r - mr), e1r = expf(d1r - mr);
    float e0o = expf(d0o - mo), e1o = expf(d1o - mo);
    float ir = 1.0f / (e0r + e1r), io = 1.0f / (e0o + e1o);
    float w0r = e0r * ir, w1r = e1r * ir;
    float w0o = e0o * io, w1o = e1o * io;

    float* outr = out + (long)t * DIM;
    float* outo = out + (long)(t + HALFM) * DIM;
    #pragma unroll
    for (int i = 0; i < 12; i++) {
        int d2 = lane + i * 32;
        float2 vr = __half22float2(Pr[384 + d2]);
        float2 vo = __half22float2(Po[384 + d2]);
        float2 a, b;
        a.x = xrv[i].x + w0r * vr.x + w1r * vo.x;
        a.y = xrv[i].y + w0r * vr.y + w1r * vo.y;
        b.x = xov[i].x + w0o * vo.x + w1o * vr.x;
        b.y = xov[i].y + w0o * vo.y + w1o * vr.y;
        *(float2*)(outr + 2 * d2) = a;
        *(float2*)(outo + 2 * d2) = b;
    }
}

// ============================================================================
// Launch
// ============================================================================
extern "C" void kernel_launch(void* const* d_in, const int* in_sizes, int n_in,
                              void* d_out, int out_size) {
    const float* x1    = (const float*)d_in[0];
    const float* x2    = (const float*)d_in[1];
    const float* Wq    = (const float*)d_in[2];
    const float* Wk    = (const float*)d_in[3];
    const float* Wv    = (const float*)d_in[4];
    const float* noise = (const float*)d_in[5];
    const float* W1    = (const float*)d_in[6];
    const float* b1    = (const float*)d_in[7];
    const float* W2    = (const float*)d_in[8];
    const float* b2    = (const float*)d_in[9];
    float* out = (float*)d_out;

    cudaFuncSetAttribute(hgemm_kernel,
                         cudaFuncAttributeMaxDynamicSharedMemorySize, SM_TOTAL);

    __half *pXc, *pWc, *pP, *pWq16, *pWk16;
    cudaGetSymbolAddress((void**)&pXc,   g_Xc);
    cudaGetSymbolAddress((void**)&pWc,   g_Wc);
    cudaGetSymbolAddress((void**)&pP,    g_P);
    cudaGetSymbolAddress((void**)&pWq16, g_Wq16);
    cudaGetSymbolAddress((void**)&pWk16, g_Wk16);

    zero_nk_kernel<<<1, 768>>>();
    nk_partial_kernel<<<dim3(6, 16), 128>>>(noise, Wk);
    c_kernel<<<96, 256>>>(Wq);
    prep_qk_kernel<<<DIM, 256>>>(Wq, Wk);
    prep_w_kernel<<<NPAD - 768, 256>>>(Wv, W1);
    prep_x_kernel<<<MTOT, 256>>>(x1, x2);

    // M-GEMM: g_Wc[j][i] = sum_e Wk[j,e] * Wq[i,e]  (rows 0..767)
    {
        dim3 grid(DIM / BN, DIM / BM);  // (6, 3)
        hgemm_kernel<<<grid, 256, SM_TOTAL>>>(pWk16, pWq16, pWc, KPB);
    }
    // Main GEMM: P = X @ [M | Wv | W1a | W1b]
    {
        dim3 grid(NPAD / BN, MTOT / BM);  // (15, 256)
        hgemm_kernel<<<grid, 256, SM_TOTAL>>>(pXc, pWc, pP, NPAD);
    }

    fusion_kernel<<<HALFM / 8, 256>>>(x1, x2, b1, W2, b2, out);
}

// round 11
// speedup vs baseline: 2.7391x; 1.0576x over previous
#include <cuda_runtime.h>
#include <cuda_fp16.h>
#include <cstdint>
#include <math.h>

// ============================================================================
//   M = Wq @ Wk^T (768x768).   c = Wq @ (noise@Wk).
//   P = X @ [M | Wv | W1a | W1b] : [65536, 1920]  (m | v | h_a | h_b)
//   d_self = (m + c).x ;  d_cross = m.x_other
// ============================================================================
#define MTOT   65536
#define HALFM  32768
#define DIM    768
#define NPAD   1920
#define KPA    768
#define KPB    768
#define KEFF   768

#define BM 128
#define BN 128
#define BK 64
#define KT (KEFF / BK)         // 12
#define STAGES 3
#define STAGE_BYTES 32768      // A 16KB + B 16KB
#define SM_TOTAL (STAGES * STAGE_BYTES)   // 96 KB -> 2 CTAs/SM

// ============================================================================
// Scratch
// ============================================================================
__device__ __half g_Xc  [(long)MTOT * KPA];
__device__ __half g_Wc  [(long)NPAD * KPB];
__device__ __half g_P   [(long)MTOT * NPAD];
__device__ __half g_Wq16[(long)DIM * DIM];
__device__ __half g_Wk16[(long)DIM * DIM];
__device__ float  g_nk[DIM];
__device__ float  g_c [DIM];

// ============================================================================
// Helpers
// ============================================================================
__device__ __forceinline__ uint32_t smem_to_u32(const void* smem_ptr) {
    uint32_t addr;
    asm("{ .reg .u64 tmp; cvta.to.shared.u64 tmp, %1; cvt.u32.u64 %0, tmp; }"
        : "=r"(addr) : "l"(smem_ptr));
    return addr;
}

#define SWZ(byte_offset) ((byte_offset) ^ ((((uint32_t)(byte_offset)) >> 3) & 0x70))

__device__ __forceinline__ void cp_async16(uint32_t dst_smem, const void* src) {
    asm volatile("cp.async.cg.shared.global [%0], [%1], 16;"
        :: "r"(dst_smem), "l"(src) : "memory");
}
#define CP_ASYNC_COMMIT()  asm volatile("cp.async.commit_group;" ::: "memory")
#define CP_ASYNC_WAIT(N)   asm volatile("cp.async.wait_group %0;" :: "n"(N) : "memory")

__device__ __forceinline__ void ldsm_x4(uint32_t* r, uint32_t addr) {
    asm volatile("ldmatrix.sync.aligned.m8n8.x4.shared.b16 {%0,%1,%2,%3}, [%4];"
        : "=r"(r[0]), "=r"(r[1]), "=r"(r[2]), "=r"(r[3]) : "r"(addr));
}

__device__ __forceinline__ void mma16816(float* c, const uint32_t* a, const uint32_t* b) {
    asm volatile(
        "mma.sync.aligned.m16n8k16.row.col.f32.f16.f16.f32 "
        "{%0,%1,%2,%3}, {%4,%5,%6,%7}, {%8,%9}, {%0,%1,%2,%3};"
        : "+f"(c[0]), "+f"(c[1]), "+f"(c[2]), "+f"(c[3])
        : "r"(a[0]), "r"(a[1]), "r"(a[2]), "r"(a[3]), "r"(b[0]), "r"(b[1]));
}

// ============================================================================
// Prep kernels
// ============================================================================
__global__ void prep_x_kernel(const float* __restrict__ x1,
                              const float* __restrict__ x2) {
    long r = blockIdx.x;
    const float* src = (r < HALFM) ? (x1 + r * DIM) : (x2 + (r - HALFM) * DIM);
    __half* dst = g_Xc + r * KPA;
    for (int c = threadIdx.x; c < DIM; c += blockDim.x)
        dst[c] = __float2half(src[c]);
}

__global__ void prep_qk_kernel(const float* __restrict__ Wq,
                               const float* __restrict__ Wk) {
    long i = blockIdx.x;
    for (int e = threadIdx.x; e < DIM; e += blockDim.x) {
        g_Wq16[i * DIM + e] = __float2half(Wq[i * DIM + e]);
        g_Wk16[i * DIM + e] = __float2half(Wk[i * DIM + e]);
    }
}

__global__ void prep_w_kernel(const float* __restrict__ Wv,
                              const float* __restrict__ W1) {
    int n = blockIdx.x + 768;  // 768..1919
    __half* dst = g_Wc + (long)n * KPB;
    for (int j = threadIdx.x; j < DIM; j += blockDim.x) {
        float w;
        if      (n < 1536) w = Wv[j * 768 + (n - 768)];
        else if (n < 1728) w = W1[j * 192 + (n - 1536)];
        else               w = W1[(768 + j) * 192 + (n - 1728)];
        dst[j] = __float2half(w);
    }
}

__global__ void zero_nk_kernel() {
    if (threadIdx.x < DIM) g_nk[threadIdx.x] = 0.0f;
}

// nk[d] = sum_j noise[j] * Wk[j*768+d]; j split over blockIdx.y (coalesced in d)
__global__ void nk_partial_kernel(const float* __restrict__ noise,
                                  const float* __restrict__ Wk) {
    const int d  = blockIdx.x * 128 + threadIdx.x;
    const int j0 = blockIdx.y * 48;
    float acc = 0.0f;
    #pragma unroll
    for (int j = 0; j < 48; j++)
        acc += noise[j0 + j] * Wk[(long)(j0 + j) * 768 + d];
    atomicAdd(&g_nk[d], acc);
}

// c[d] = Wq[d,:] . nk  — one warp per d, lane-strided coalesced reads
__global__ void c_kernel(const float* __restrict__ Wq) {
    const int wid  = threadIdx.x >> 5;
    const int lane = threadIdx.x & 31;
    const int d    = blockIdx.x * 8 + wid;
    float acc = 0.0f;
    #pragma unroll
    for (int i = 0; i < 24; i++) {
        int e = lane + i * 32;
        acc += Wq[(long)d * 768 + e] * g_nk[e];
    }
    #pragma unroll
    for (int o = 16; o; o >>= 1) acc += __shfl_xor_sync(0xFFFFFFFFu, acc, o);
    if (lane == 0) g_c[d] = acc;
}

// ============================================================================
// fp16 GEMM: C[m][n] = sum_k A[m][k]*B[n][k], K=768.
// BM=BN=128, BK=64. 8 warps (4 m x 2 n), 32x64 warp tiles, 3-stage, 2 CTA/SM.
// (R6-proven configuration: co-resident CTA hides barrier+LDSM bubbles.)
// ============================================================================
__global__ void __launch_bounds__(256, 2)
hgemm_kernel(const __half* __restrict__ A, const __half* __restrict__ B,
             __half* __restrict__ C, int ldc) {
    extern __shared__ char smem[];
    const uint32_t sbase = smem_to_u32(smem);
    const int tid    = threadIdx.x;
    const int wid    = tid >> 5;
    const int lane   = tid & 31;
    const int warp_m = wid & 3;   // 0..3, 32 rows each
    const int warp_n = wid >> 2;  // 0..1, 64 cols each
    const int m0 = blockIdx.y * BM;
    const int n0 = blockIdx.x * BN;

    const __half* Ag = A + (long)m0 * KPA;
    const __half* Bg = B + (long)n0 * KPB;

    auto load_stage = [&](int kt, int st) {
        const int k0 = kt * BK;
        const uint32_t aT = sbase + st * STAGE_BYTES;
        const uint32_t bT = aT + 16384;
        #pragma unroll
        for (int i = 0; i < 4; i++) {
            int idx = tid + i * 256;
            int row = idx >> 3, c = idx & 7;
            cp_async16(aT + SWZ((uint32_t)(row * 128 + c * 16)),
                       (const char*)(Ag + (long)row * KPA + k0) + c * 16);
        }
        #pragma unroll
        for (int i = 0; i < 4; i++) {
            int idx = tid + i * 256;
            int row = idx >> 3, c = idx & 7;
            cp_async16(bT + SWZ((uint32_t)(row * 128 + c * 16)),
                       (const char*)(Bg + (long)row * KPB + k0) + c * 16);
        }
        CP_ASYNC_COMMIT();
    };

    float acc[2][8][4];
    #pragma unroll
    for (int mm = 0; mm < 2; mm++)
        #pragma unroll
        for (int nt = 0; nt < 8; nt++)
            #pragma unroll
            for (int q = 0; q < 4; q++) acc[mm][nt][q] = 0.0f;

    load_stage(0, 0);
    load_stage(1, 1);

    const int rA  = warp_m * 32 + (lane & 7) + ((lane >> 3) & 1) * 8;
    const int kbA = ((lane >> 4) & 1) * 16;
    const int rB  = warp_n * 64 + (lane & 7) + ((lane >> 4) & 1) * 8;
    const int kbB = ((lane >> 3) & 1) * 16;

    for (int kt = 0; kt < KT; kt++) {
        if (kt + 1 < KT) { CP_ASYNC_WAIT(1); } else { CP_ASYNC_WAIT(0); }
        __syncthreads();
        if (kt + 2 < KT) load_stage(kt + 2, (kt + 2) % STAGES);

        const uint32_t aT = sbase + (kt % STAGES) * STAGE_BYTES;
        const uint32_t bT = aT + 16384;

        #pragma unroll
        for (int ks = 0; ks < 4; ks++) {
            uint32_t a[2][4];
            ldsm_x4(a[0], aT + SWZ((uint32_t)(rA * 128 + ks * 32 + kbA)));
            ldsm_x4(a[1], aT + SWZ((uint32_t)((rA + 16) * 128 + ks * 32 + kbA)));
            uint32_t b[8][2];
            #pragma unroll
            for (int g = 0; g < 4; g++) {
                uint32_t t[4];
                ldsm_x4(t, bT + SWZ((uint32_t)((rB + g * 16) * 128 + ks * 32 + kbB)));
                b[2 * g][0]     = t[0]; b[2 * g][1]     = t[1];
                b[2 * g + 1][0] = t[2]; b[2 * g + 1][1] = t[3];
            }
            #pragma unroll
            for (int mm = 0; mm < 2; mm++)
                #pragma unroll
                for (int nt = 0; nt < 8; nt++)
                    mma16816(acc[mm][nt], a[mm], b[nt]);
        }
        // single barrier per k-tile: stage (kt+2)%3 was last read at kt-1,
        // strictly before this iteration's barrier.
    }

    // Epilogue: fp16 half2 stores
    const int gid = lane >> 2, tig = lane & 3;
    #pragma unroll
    for (int mm = 0; mm < 2; mm++) {
        const long mrow = (long)(m0 + warp_m * 32 + mm * 16 + gid);
        __half* base0 = C + mrow * ldc + n0 + warp_n * 64 + tig * 2;
        __half* base1 = base0 + 8L * ldc;
        #pragma unroll
        for (int nt = 0; nt < 8; nt++) {
            *(__half2*)(base0 + nt * 8) =
                __floats2half2_rn(acc[mm][nt][0], acc[mm][nt][1]);
            *(__half2*)(base1 + nt * 8) =
                __floats2half2_rn(acc[mm][nt][2], acc[mm][nt][3]);
        }
    }
}

// ============================================================================
// Fusion: one warp per token PAIR (r, r+32768); m and x read once per pair.
//   P row layout (half2 units): [m(384) | v(384) | h_a(96) | h_b(96)]
// ============================================================================
__global__ void __launch_bounds__(256) fusion_kernel(
    const float* __restrict__ x1, const float* __restrict__ x2,
    const float* __restrict__ b1, const float* __restrict__ W2,
    const float* __restrict__ b2, float* __restrict__ out) {
    const int t   = blockIdx.x * 8 + (threadIdx.x >> 5);  // pair id 0..32767
    const int lane = threadIdx.x & 31;
    const __half2* Pr = (const __half2*)g_P + (long)t * (NPAD / 2);
    const __half2* Po = (const __half2*)g_P + (long)(t + HALFM) * (NPAD / 2);
    const float* xr = x1 + (long)t * DIM;
    const float* xo = x2 + (long)t * DIM;

    float ds_r = 0.0f, dc_r = 0.0f, ds_o = 0.0f, dc_o = 0.0f;
    float2 xrv[12], xov[12];
    #pragma unroll
    for (int i = 0; i < 12; i++) {
        int d2 = lane + i * 32;
        float2 mr = __half22float2(Pr[d2]);
        float2 mo = __half22float2(Po[d2]);
        float2 xs = *(const float2*)(xr + 2 * d2);
        float2 xq = *(const float2*)(xo + 2 * d2);
        float2 cc = *(const float2*)(g_c + 2 * d2);
        xrv[i] = xs; xov[i] = xq;
        ds_r += (mr.x + cc.x) * xs.x + (mr.y + cc.y) * xs.y;
        dc_r += mr.x * xq.x + mr.y * xq.y;
        ds_o += (mo.x + cc.x) * xq.x + (mo.y + cc.y) * xq.y;
        dc_o += mo.x * xs.x + mo.y * xs.y;
    }
    float ha_r = 0.0f, ha_o = 0.0f;
    #pragma unroll
    for (int i = 0; i < 3; i++) {
        int j2 = lane + i * 32;
        float2 ar = __half22float2(Pr[768 + j2]);   // h_a(r)
        float2 br = __half22float2(Pr[864 + j2]);   // h_b(r)
        float2 ao = __half22float2(Po[768 + j2]);   // h_a(o)
        float2 bo = __half22float2(Po[864 + j2]);   // h_b(o)
        float2 bb = *(const float2*)(b1 + 2 * j2);
        float2 ww = *(const float2*)(W2 + 2 * j2);
        float r0 = ar.x + bo.x + bb.x, r1 = ar.y + bo.y + bb.y;
        float o0 = ao.x + br.x + bb.x, o1 = ao.y + br.y + bb.y;
        r0 = 0.5f * r0 * (1.0f + erff(r0 * 0.7071067811865476f));
        r1 = 0.5f * r1 * (1.0f + erff(r1 * 0.7071067811865476f));
        o0 = 0.5f * o0 * (1.0f + erff(o0 * 0.7071067811865476f));
        o1 = 0.5f * o1 * (1.0f + erff(o1 * 0.7071067811865476f));
        ha_r += r0 * ww.x + r1 * ww.y;
        ha_o += o0 * ww.x + o1 * ww.y;
    }
    #pragma unroll
    for (int o = 16; o; o >>= 1) {
        ds_r += __shfl_xor_sync(0xFFFFFFFFu, ds_r, o);
        dc_r += __shfl_xor_sync(0xFFFFFFFFu, dc_r, o);
        ds_o += __shfl_xor_sync(0xFFFFFFFFu, ds_o, o);
        dc_o += __shfl_xor_sync(0xFFFFFFFFu, dc_o, o);
        ha_r += __shfl_xor_sync(0xFFFFFFFFu, ha_r, o);
        ha_o += __shfl_xor_sync(0xFFFFFFFFu, ha_o, o);
    }
    const float bias = b2[0];
    const float SCALE = 0.03608439182435161f;  // 768^-0.5
    float rel_r = 1.0f / (1.0f + expf(-(ha_r + bias)));
    float rel_o = 1.0f / (1.0f + expf(-(ha_o + bias)));
    float d0r = ds_r * SCALE, d1r = dc_r * rel_r * SCALE;
    float d0o = ds_o * SCALE, d1o = dc_o * rel_o * SCALE;
    float mr = fmaxf(d0r, d1r), mo = fmaxf(d0o, d1o);
    float e0r = expf(d0r - mr), e1r = expf(d1r - mr);
    float e0o = expf(d0o - mo), e1o = expf(d1o - mo);
    float ir = 1.0f / (e0r + e1r), io = 1.0f / (e0o + e1o);
    float w0r = e0r * ir, w1r = e1r * ir;
    float w0o = e0o * io, w1o = e1o * io;

    float* outr = out + (long)t * DIM;
    float* outo = out + (long)(t + HALFM) * DIM;
    #pragma unroll
    for (int i = 0; i < 12; i++) {
        int d2 = lane + i * 32;
        float2 vr = __half22float2(Pr[384 + d2]);
        float2 vo = __half22float2(Po[384 + d2]);
        float2 a, b;
        a.x = xrv[i].x + w0r * vr.x + w1r * vo.x;
        a.y = xrv[i].y + w0r * vr.y + w1r * vo.y;
        b.x = xov[i].x + w0o * vo.x + w1o * vr.x;
        b.y = xov[i].y + w0o * vo.y + w1o * vr.y;
        *(float2*)(outr + 2 * d2) = a;
        *(float2*)(outo + 2 * d2) = b;
    }
}

// ============================================================================
// Launch
// ============================================================================
extern "C" void kernel_launch(void* const* d_in, const int* in_sizes, int n_in,
                              void* d_out, int out_size) {
    const float* x1    = (const float*)d_in[0];
    const float* x2    = (const float*)d_in[1];
    const float* Wq    = (const float*)d_in[2];
    const float* Wk    = (const float*)d_in[3];
    const float* Wv    = (const float*)d_in[4];
    const float* noise = (const float*)d_in[5];
    const float* W1    = (const float*)d_in[6];
    const float* b1    = (const float*)d_in[7];
    const float* W2    = (const float*)d_in[8];
    const float* b2    = (const float*)d_in[9];
    float* out = (float*)d_out;

    cudaFuncSetAttribute(hgemm_kernel,
                         cudaFuncAttributeMaxDynamicSharedMemorySize, SM_TOTAL);

    __half *pXc, *pWc, *pP, *pWq16, *pWk16;
    cudaGetSymbolAddress((void**)&pXc,   g_Xc);
    cudaGetSymbolAddress((void**)&pWc,   g_Wc);
    cudaGetSymbolAddress((void**)&pP,    g_P);
    cudaGetSymbolAddress((void**)&pWq16, g_Wq16);
    cudaGetSymbolAddress((void**)&pWk16, g_Wk16);

    zero_nk_kernel<<<1, 768>>>();
    nk_partial_kernel<<<dim3(6, 16), 128>>>(noise, Wk);
    c_kernel<<<96, 256>>>(Wq);
    prep_qk_kernel<<<DIM, 256>>>(Wq, Wk);
    prep_w_kernel<<<NPAD - 768, 256>>>(Wv, W1);
    prep_x_kernel<<<MTOT, 256>>>(x1, x2);

    // M-GEMM: g_Wc[j][i] = sum_e Wk[j,e] * Wq[i,e]  (rows 0..767)
    {
        dim3 grid(DIM / BN, DIM / BM);  // (6, 6)
        hgemm_kernel<<<grid, 256, SM_TOTAL>>>(pWk16, pWq16, pWc, KPB);
    }
    // Main GEMM: P = X @ [M | Wv | W1a | W1b]
    {
        dim3 grid(NPAD / BN, MTOT / BM);  // (15, 512)
        hgemm_kernel<<<grid, 256, SM_TOTAL>>>(pXc, pWc, pP, NPAD);
    }

    fusion_kernel<<<HALFM / 8, 256>>>(x1, x2, b1, W2, b2, out);
}

// round 12
// speedup vs baseline: 2.9752x; 1.0862x over previous
#include <cuda_runtime.h>
#include <cuda_fp16.h>
#include <cstdint>
#include <math.h>

// ============================================================================
//   M = Wq @ Wk^T (768x768).   c = Wq @ (noise@Wk).
//   P = X @ [M | Wv | W1a | W1b] : [65536, 1920]  (m | v | h_a | h_b)
//   d_self = (m + c).x ;  d_cross = m.x_other
// ============================================================================
#define MTOT   65536
#define HALFM  32768
#define DIM    768
#define NPAD   1920
#define KPA    768
#define KPB    768
#define KEFF   768

#define BM 128
#define BN 128
#define BK 64
#define KT (KEFF / BK)         // 12
#define STAGES 3
#define STAGE_BYTES 32768      // A 16KB + B 16KB
#define SM_TOTAL (STAGES * STAGE_BYTES)   // 96 KB -> 2 CTAs/SM

// ============================================================================
// Scratch
// ============================================================================
__device__ __half g_Xc  [(long)MTOT * KPA];
__device__ __half g_Wc  [(long)NPAD * KPB];
__device__ __half g_P   [(long)MTOT * NPAD];
__device__ __half g_Wq16[(long)DIM * DIM];
__device__ __half g_Wk16[(long)DIM * DIM];
__device__ float  g_nk[DIM];
__device__ float  g_c [DIM];

// ============================================================================
// Helpers
// ============================================================================
__device__ __forceinline__ uint32_t smem_to_u32(const void* smem_ptr) {
    uint32_t addr;
    asm("{ .reg .u64 tmp; cvta.to.shared.u64 tmp, %1; cvt.u32.u64 %0, tmp; }"
        : "=r"(addr) : "l"(smem_ptr));
    return addr;
}

#define SWZ(byte_offset) ((byte_offset) ^ ((((uint32_t)(byte_offset)) >> 3) & 0x70))

__device__ __forceinline__ void cp_async16(uint32_t dst_smem, const void* src) {
    asm volatile("cp.async.cg.shared.global [%0], [%1], 16;"
        :: "r"(dst_smem), "l"(src) : "memory");
}
#define CP_ASYNC_COMMIT()  asm volatile("cp.async.commit_group;" ::: "memory")
#define CP_ASYNC_WAIT(N)   asm volatile("cp.async.wait_group %0;" :: "n"(N) : "memory")

__device__ __forceinline__ void ldsm_x4(uint32_t* r, uint32_t addr) {
    asm volatile("ldmatrix.sync.aligned.m8n8.x4.shared.b16 {%0,%1,%2,%3}, [%4];"
        : "=r"(r[0]), "=r"(r[1]), "=r"(r[2]), "=r"(r[3]) : "r"(addr));
}

__device__ __forceinline__ void mma16816(float* c, const uint32_t* a, const uint32_t* b) {
    asm volatile(
        "mma.sync.aligned.m16n8k16.row.col.f32.f16.f16.f32 "
        "{%0,%1,%2,%3}, {%4,%5,%6,%7}, {%8,%9}, {%0,%1,%2,%3};"
        : "+f"(c[0]), "+f"(c[1]), "+f"(c[2]), "+f"(c[3])
        : "r"(a[0]), "r"(a[1]), "r"(a[2]), "r"(a[3]), "r"(b[0]), "r"(b[1]));
}

// ============================================================================
// Prep kernels
// ============================================================================
// g_Xc is exactly [x1;x2] row-major -> flat float4 -> half4 conversion
#define N4H ((long)HALFM * DIM / 4)   // float4 count per input
__global__ void prep_x_kernel(const float4* __restrict__ x1,
                              const float4* __restrict__ x2) {
    long i = (long)blockIdx.x * blockDim.x + threadIdx.x;
    float4 v = (i < N4H) ? x1[i] : x2[i - N4H];
    __half2 lo = __floats2half2_rn(v.x, v.y);
    __half2 hi = __floats2half2_rn(v.z, v.w);
    uint2 pack;
    pack.x = *(uint32_t*)&lo;
    pack.y = *(uint32_t*)&hi;
    ((uint2*)g_Xc)[i] = pack;
}

__global__ void prep_qk_kernel(const float* __restrict__ Wq,
                               const float* __restrict__ Wk) {
    long i = blockIdx.x;
    for (int e = threadIdx.x; e < DIM; e += blockDim.x) {
        g_Wq16[i * DIM + e] = __float2half(Wq[i * DIM + e]);
        g_Wk16[i * DIM + e] = __float2half(Wk[i * DIM + e]);
    }
}

__global__ void prep_w_kernel(const float* __restrict__ Wv,
                              const float* __restrict__ W1) {
    int n = blockIdx.x + 768;  // 768..1919
    __half* dst = g_Wc + (long)n * KPB;
    for (int j = threadIdx.x; j < DIM; j += blockDim.x) {
        float w;
        if      (n < 1536) w = Wv[j * 768 + (n - 768)];
        else if (n < 1728) w = W1[j * 192 + (n - 1536)];
        else               w = W1[(768 + j) * 192 + (n - 1728)];
        dst[j] = __float2half(w);
    }
}

__global__ void zero_nk_kernel() {
    if (threadIdx.x < DIM) g_nk[threadIdx.x] = 0.0f;
}

__global__ void nk_partial_kernel(const float* __restrict__ noise,
                                  const float* __restrict__ Wk) {
    const int d  = blockIdx.x * 128 + threadIdx.x;
    const int j0 = blockIdx.y * 48;
    float acc = 0.0f;
    #pragma unroll
    for (int j = 0; j < 48; j++)
        acc += noise[j0 + j] * Wk[(long)(j0 + j) * 768 + d];
    atomicAdd(&g_nk[d], acc);
}

__global__ void c_kernel(const float* __restrict__ Wq) {
    const int wid  = threadIdx.x >> 5;
    const int lane = threadIdx.x & 31;
    const int d    = blockIdx.x * 8 + wid;
    float acc = 0.0f;
    #pragma unroll
    for (int i = 0; i < 24; i++) {
        int e = lane + i * 32;
        acc += Wq[(long)d * 768 + e] * g_nk[e];
    }
    #pragma unroll
    for (int o = 16; o; o >>= 1) acc += __shfl_xor_sync(0xFFFFFFFFu, acc, o);
    if (lane == 0) g_c[d] = acc;
}

// ============================================================================
// fp16 GEMM: C[m][n] = sum_k A[m][k]*B[n][k], K=768.
// BM=BN=128, BK=64. 128 threads, 4 warps (2m x 2n), 64x64 warp tiles,
// 3-stage cp.async, 96 KB smem, 2 CTAs/SM (barrier hiding preserved).
// Per k-step per warp: 8 LDSM : 32 HMMA (was 6:16) -> higher tensor ceiling.
// ============================================================================
__global__ void __launch_bounds__(128, 2)
hgemm_kernel(const __half* __restrict__ A, const __half* __restrict__ B,
             __half* __restrict__ C, int ldc) {
    extern __shared__ char smem[];
    const uint32_t sbase = smem_to_u32(smem);
    const int tid    = threadIdx.x;
    const int wid    = tid >> 5;
    const int lane   = tid & 31;
    const int warp_m = wid >> 1;  // 0..1, 64 rows each
    const int warp_n = wid & 1;   // 0..1, 64 cols each
    const int m0 = blockIdx.y * BM;
    const int n0 = blockIdx.x * BN;

    const __half* Ag = A + (long)m0 * KPA;
    const __half* Bg = B + (long)n0 * KPB;

    auto load_stage = [&](int kt, int st) {
        const int k0 = kt * BK;
        const uint32_t aT = sbase + st * STAGE_BYTES;
        const uint32_t bT = aT + 16384;
        #pragma unroll
        for (int i = 0; i < 8; i++) {
            int idx = tid + i * 128;
            int row = idx >> 3, c = idx & 7;
            cp_async16(aT + SWZ((uint32_t)(row * 128 + c * 16)),
                       (const char*)(Ag + (long)row * KPA + k0) + c * 16);
        }
        #pragma unroll
        for (int i = 0; i < 8; i++) {
            int idx = tid + i * 128;
            int row = idx >> 3, c = idx & 7;
            cp_async16(bT + SWZ((uint32_t)(row * 128 + c * 16)),
                       (const char*)(Bg + (long)row * KPB + k0) + c * 16);
        }
        CP_ASYNC_COMMIT();
    };

    float acc[4][8][4];
    #pragma unroll
    for (int mm = 0; mm < 4; mm++)
        #pragma unroll
        for (int nt = 0; nt < 8; nt++)
            #pragma unroll
            for (int q = 0; q < 4; q++) acc[mm][nt][q] = 0.0f;

    load_stage(0, 0);
    load_stage(1, 1);

    const int rA  = warp_m * 64 + (lane & 7) + ((lane >> 3) & 1) * 8;
    const int kbA = ((lane >> 4) & 1) * 16;
    const int rB  = warp_n * 64 + (lane & 7) + ((lane >> 4) & 1) * 8;
    const int kbB = ((lane >> 3) & 1) * 16;

    for (int kt = 0; kt < KT; kt++) {
        if (kt + 1 < KT) { CP_ASYNC_WAIT(1); } else { CP_ASYNC_WAIT(0); }
        __syncthreads();
        if (kt + 2 < KT) load_stage(kt + 2, (kt + 2) % STAGES);

        const uint32_t aT = sbase + (kt % STAGES) * STAGE_BYTES;
        const uint32_t bT = aT + 16384;

        #pragma unroll
        for (int ks = 0; ks < 4; ks++) {
            uint32_t a[4][4];
            #pragma unroll
            for (int mm = 0; mm < 4; mm++)
                ldsm_x4(a[mm], aT + SWZ((uint32_t)((rA + mm * 16) * 128 +
                                                   ks * 32 + kbA)));
            #pragma unroll
            for (int g = 0; g < 4; g++) {
                uint32_t t[4];
                ldsm_x4(t, bT + SWZ((uint32_t)((rB + g * 16) * 128 +
                                               ks * 32 + kbB)));
                #pragma unroll
                for (int mm = 0; mm < 4; mm++) {
                    mma16816(acc[mm][2 * g],     a[mm], t);
                    mma16816(acc[mm][2 * g + 1], a[mm], t + 2);
                }
            }
        }
        // single barrier per k-tile: stage (kt+2)%3 was last read at kt-1,
        // strictly before this iteration's barrier.
    }

    // Epilogue: fp16 half2 stores
    const int gid = lane >> 2, tig = lane & 3;
    #pragma unroll
    for (int mm = 0; mm < 4; mm++) {
        const long mrow = (long)(m0 + warp_m * 64 + mm * 16 + gid);
        __half* base0 = C + mrow * ldc + n0 + warp_n * 64 + tig * 2;
        __half* base1 = base0 + 8L * ldc;
        #pragma unroll
        for (int nt = 0; nt < 8; nt++) {
            *(__half2*)(base0 + nt * 8) =
                __floats2half2_rn(acc[mm][nt][0], acc[mm][nt][1]);
            *(__half2*)(base1 + nt * 8) =
                __floats2half2_rn(acc[mm][nt][2], acc[mm][nt][3]);
        }
    }
}

// ============================================================================
// Fusion: one warp per token PAIR (r, r+32768); m and x read once per pair.
//   P row layout (half2 units): [m(384) | v(384) | h_a(96) | h_b(96)]
// ============================================================================
__global__ void __launch_bounds__(256) fusion_kernel(
    const float* __restrict__ x1, const float* __restrict__ x2,
    const float* __restrict__ b1, const float* __restrict__ W2,
    const float* __restrict__ b2, float* __restrict__ out) {
    const int t   = blockIdx.x * 8 + (threadIdx.x >> 5);  // pair id 0..32767
    const int lane = threadIdx.x & 31;
    const __half2* Pr = (const __half2*)g_P + (long)t * (NPAD / 2);
    const __half2* Po = (const __half2*)g_P + (long)(t + HALFM) * (NPAD / 2);
    const float* xr = x1 + (long)t * DIM;
    const float* xo = x2 + (long)t * DIM;

    float ds_r = 0.0f, dc_r = 0.0f, ds_o = 0.0f, dc_o = 0.0f;
    float2 xrv[12], xov[12];
    #pragma unroll
    for (int i = 0; i < 12; i++) {
        int d2 = lane + i * 32;
        float2 mr = __half22float2(Pr[d2]);
        float2 mo = __half22float2(Po[d2]);
        float2 xs = *(const float2*)(xr + 2 * d2);
        float2 xq = *(const float2*)(xo + 2 * d2);
        float2 cc = *(const float2*)(g_c + 2 * d2);
        xrv[i] = xs; xov[i] = xq;
        ds_r += (mr.x + cc.x) * xs.x + (mr.y + cc.y) * xs.y;
        dc_r += mr.x * xq.x + mr.y * xq.y;
        ds_o += (mo.x + cc.x) * xq.x + (mo.y + cc.y) * xq.y;
        dc_o += mo.x * xs.x + mo.y * xs.y;
    }
    float ha_r = 0.0f, ha_o = 0.0f;
    #pragma unroll
    for (int i = 0; i < 3; i++) {
        int j2 = lane + i * 32;
        float2 ar = __half22float2(Pr[768 + j2]);   // h_a(r)
        float2 br = __half22float2(Pr[864 + j2]);   // h_b(r)
        float2 ao = __half22float2(Po[768 + j2]);   // h_a(o)
        float2 bo = __half22float2(Po[864 + j2]);   // h_b(o)
        float2 bb = *(const float2*)(b1 + 2 * j2);
        float2 ww = *(const float2*)(W2 + 2 * j2);
        float r0 = ar.x + bo.x + bb.x, r1 = ar.y + bo.y + bb.y;
        float o0 = ao.x + br.x + bb.x, o1 = ao.y + br.y + bb.y;
        r0 = 0.5f * r0 * (1.0f + erff(r0 * 0.7071067811865476f));
        r1 = 0.5f * r1 * (1.0f + erff(r1 * 0.7071067811865476f));
        o0 = 0.5f * o0 * (1.0f + erff(o0 * 0.7071067811865476f));
        o1 = 0.5f * o1 * (1.0f + erff(o1 * 0.7071067811865476f));
        ha_r += r0 * ww.x + r1 * ww.y;
        ha_o += o0 * ww.x + o1 * ww.y;
    }
    #pragma unroll
    for (int o = 16; o; o >>= 1) {
        ds_r += __shfl_xor_sync(0xFFFFFFFFu, ds_r, o);
        dc_r += __shfl_xor_sync(0xFFFFFFFFu, dc_r, o);
        ds_o += __shfl_xor_sync(0xFFFFFFFFu, ds_o, o);
        dc_o += __shfl_xor_sync(0xFFFFFFFFu, dc_o, o);
        ha_r += __shfl_xor_sync(0xFFFFFFFFu, ha_r, o);
        ha_o += __shfl_xor_sync(0xFFFFFFFFu, ha_o, o);
    }
    const float bias = b2[0];
    const float SCALE = 0.03608439182435161f;  // 768^-0.5
    float rel_r = 1.0f / (1.0f + expf(-(ha_r + bias)));
    float rel_o = 1.0f / (1.0f + expf(-(ha_o + bias)));
    float d0r = ds_r * SCALE, d1r = dc_r * rel_r * SCALE;
    float d0o = ds_o * SCALE, d1o = dc_o * rel_o * SCALE;
    float mr = fmaxf(d0r, d1r), mo = fmaxf(d0o, d1o);
    float e0r = expf(d0r - mr), e1r = expf(d1r - mr);
    float e0o = expf(d0o - mo), e1o = expf(d1o - mo);
    float ir = 1.0f / (e0r + e1r), io = 1.0f / (e0o + e1o);
    float w0r = e0r * ir, w1r = e1r * ir;
    float w0o = e0o * io, w1o = e1o * io;

    float* outr = out + (long)t * DIM;
    float* outo = out + (long)(t + HALFM) * DIM;
    #pragma unroll
    for (int i = 0; i < 12; i++) {
        int d2 = lane + i * 32;
        float2 vr = __half22float2(Pr[384 + d2]);
        float2 vo = __half22float2(Po[384 + d2]);
        float2 a, b;
        a.x = xrv[i].x + w0r * vr.x + w1r * vo.x;
        a.y = xrv[i].y + w0r * vr.y + w1r * vo.y;
        b.x = xov[i].x + w0o * vo.x + w1o * vr.x;
        b.y = xov[i].y + w0o * vo.y + w1o * vr.y;
        *(float2*)(outr + 2 * d2) = a;
        *(float2*)(outo + 2 * d2) = b;
    }
}

// ============================================================================
// Launch
// ============================================================================
extern "C" void kernel_launch(void* const* d_in, const int* in_sizes, int n_in,
                              void* d_out, int out_size) {
    const float* x1    = (const float*)d_in[0];
    const float* x2    = (const float*)d_in[1];
    const float* Wq    = (const float*)d_in[2];
    const float* Wk    = (const float*)d_in[3];
    const float* Wv    = (const float*)d_in[4];
    const float* noise = (const float*)d_in[5];
    const float* W1    = (const float*)d_in[6];
    const float* b1    = (const float*)d_in[7];
    const float* W2    = (const float*)d_in[8];
    const float* b2    = (const float*)d_in[9];
    float* out = (float*)d_out;

    cudaFuncSetAttribute(hgemm_kernel,
                         cudaFuncAttributeMaxDynamicSharedMemorySize, SM_TOTAL);

    __half *pXc, *pWc, *pP, *pWq16, *pWk16;
    cudaGetSymbolAddress((void**)&pXc,   g_Xc);
    cudaGetSymbolAddress((void**)&pWc,   g_Wc);
    cudaGetSymbolAddress((void**)&pP,    g_P);
    cudaGetSymbolAddress((void**)&pWq16, g_Wq16);
    cudaGetSymbolAddress((void**)&pWk16, g_Wk16);

    zero_nk_kernel<<<1, 768>>>();
    nk_partial_kernel<<<dim3(6, 16), 128>>>(noise, Wk);
    c_kernel<<<96, 256>>>(Wq);
    prep_qk_kernel<<<DIM, 256>>>(Wq, Wk);
    prep_w_kernel<<<NPAD - 768, 256>>>(Wv, W1);
    prep_x_kernel<<<(unsigned)(2 * N4H / 256), 256>>>((const float4*)x1,
                                                      (const float4*)x2);

    // M-GEMM: g_Wc[j][i] = sum_e Wk[j,e] * Wq[i,e]  (rows 0..767)
    {
        dim3 grid(DIM / BN, DIM / BM);  // (6, 6)
        hgemm_kernel<<<grid, 128, SM_TOTAL>>>(pWk16, pWq16, pWc, KPB);
    }
    // Main GEMM: P = X @ [M | Wv | W1a | W1b]
    {
        dim3 grid(NPAD / BN, MTOT / BM);  // (15, 512)
        hgemm_kernel<<<grid, 128, SM_TOTAL>>>(pXc, pWc, pP, NPAD);
    }

    fusion_kernel<<<HALFM / 8, 256>>>(x1, x2, b1, W2, b2, out);
}

// round 13
// speedup vs baseline: 3.1828x; 1.0698x over previous
#include <cuda_runtime.h>
#include <cuda_fp16.h>
#include <cstdint>
#include <math.h>

// ============================================================================
//   M = Wq @ Wk^T (768x768).   c = Wq @ (noise@Wk).
//   P = X @ [M | Wv | W1a | W1b] : [65536, 1920]  (m | v | h_a | h_b)
//   d_self = (m + c).x ;  d_cross = m.x_other
// ============================================================================
#define MTOT   65536
#define HALFM  32768
#define DIM    768
#define NPAD   1920
#define KPA    768
#define KPB    768
#define KEFF   768

#define BM 128
#define BN 128
#define BK 64
#define KT (KEFF / BK)         // 12
#define STAGES 3
#define STAGE_BYTES 32768      // A 16KB + B 16KB
#define SM_TOTAL (STAGES * STAGE_BYTES)   // 96 KB -> 2 CTAs/SM

// ============================================================================
// Scratch
// ============================================================================
__device__ __half g_Xc  [(long)MTOT * KPA];
__device__ __half g_Wc  [(long)NPAD * KPB];
__device__ __half g_P   [(long)MTOT * NPAD];
__device__ __half g_Wq16[(long)DIM * DIM];
__device__ __half g_Wk16[(long)DIM * DIM];
__device__ float  g_nk[DIM];
__device__ float  g_c [DIM];

// ============================================================================
// Helpers
// ============================================================================
__device__ __forceinline__ uint32_t smem_to_u32(const void* smem_ptr) {
    uint32_t addr;
    asm("{ .reg .u64 tmp; cvta.to.shared.u64 tmp, %1; cvt.u32.u64 %0, tmp; }"
        : "=r"(addr) : "l"(smem_ptr));
    return addr;
}

#define SWZ(byte_offset) ((byte_offset) ^ ((((uint32_t)(byte_offset)) >> 3) & 0x70))

__device__ __forceinline__ void cp_async16(uint32_t dst_smem, const void* src) {
    asm volatile("cp.async.cg.shared.global [%0], [%1], 16;"
        :: "r"(dst_smem), "l"(src) : "memory");
}
#define CP_ASYNC_COMMIT()  asm volatile("cp.async.commit_group;" ::: "memory")
#define CP_ASYNC_WAIT(N)   asm volatile("cp.async.wait_group %0;" :: "n"(N) : "memory")

__device__ __forceinline__ void ldsm_x4(uint32_t* r, uint32_t addr) {
    asm volatile("ldmatrix.sync.aligned.m8n8.x4.shared.b16 {%0,%1,%2,%3}, [%4];"
        : "=r"(r[0]), "=r"(r[1]), "=r"(r[2]), "=r"(r[3]) : "r"(addr));
}

__device__ __forceinline__ void mma16816(float* c, const uint32_t* a, const uint32_t* b) {
    asm volatile(
        "mma.sync.aligned.m16n8k16.row.col.f32.f16.f16.f32 "
        "{%0,%1,%2,%3}, {%4,%5,%6,%7}, {%8,%9}, {%0,%1,%2,%3};"
        : "+f"(c[0]), "+f"(c[1]), "+f"(c[2]), "+f"(c[3])
        : "r"(a[0]), "r"(a[1]), "r"(a[2]), "r"(a[3]), "r"(b[0]), "r"(b[1]));
}

// ============================================================================
// Prep kernels
// ============================================================================
#define N4H   ((long)HALFM * DIM / 4)        // float4 count per input (6291456)
#define XBLK  ((unsigned)(2 * N4H / 256))    // 49152 blocks for x conversion

// One kernel: [0,768) qk rows | [768,1920) w rows | [1920,..) x float4 chunks
__global__ void prep_all_kernel(const float*  __restrict__ Wq,
                                const float*  __restrict__ Wk,
                                const float*  __restrict__ Wv,
                                const float*  __restrict__ W1,
                                const float4* __restrict__ x1,
                                const float4* __restrict__ x2) {
    const int b = blockIdx.x;
    if (b < 768) {
        long i = b;
        for (int e = threadIdx.x; e < DIM; e += blockDim.x) {
            g_Wq16[i * DIM + e] = __float2half(Wq[i * DIM + e]);
            g_Wk16[i * DIM + e] = __float2half(Wk[i * DIM + e]);
        }
    } else if (b < 1920) {
        int n = b;  // 768..1919
        __half* dst = g_Wc + (long)n * KPB;
        for (int j = threadIdx.x; j < DIM; j += blockDim.x) {
            float w;
            if      (n < 1536) w = Wv[j * 768 + (n - 768)];
            else if (n < 1728) w = W1[j * 192 + (n - 1536)];
            else               w = W1[(768 + j) * 192 + (n - 1728)];
            dst[j] = __float2half(w);
        }
    } else {
        long i = (long)(b - 1920) * 256 + threadIdx.x;
        float4 v = (i < N4H) ? x1[i] : x2[i - N4H];
        __half2 lo = __floats2half2_rn(v.x, v.y);
        __half2 hi = __floats2half2_rn(v.z, v.w);
        uint2 pack;
        pack.x = *(uint32_t*)&lo;
        pack.y = *(uint32_t*)&hi;
        ((uint2*)g_Xc)[i] = pack;
    }
}

__global__ void zero_nk_kernel() {
    if (threadIdx.x < DIM) g_nk[threadIdx.x] = 0.0f;
}

__global__ void nk_partial_kernel(const float* __restrict__ noise,
                                  const float* __restrict__ Wk) {
    const int d  = blockIdx.x * 128 + threadIdx.x;
    const int j0 = blockIdx.y * 48;
    float acc = 0.0f;
    #pragma unroll
    for (int j = 0; j < 48; j++)
        acc += noise[j0 + j] * Wk[(long)(j0 + j) * 768 + d];
    atomicAdd(&g_nk[d], acc);
}

__global__ void c_kernel(const float* __restrict__ Wq) {
    const int wid  = threadIdx.x >> 5;
    const int lane = threadIdx.x & 31;
    const int d    = blockIdx.x * 8 + wid;
    float acc = 0.0f;
    #pragma unroll
    for (int i = 0; i < 24; i++) {
        int e = lane + i * 32;
        acc += Wq[(long)d * 768 + e] * g_nk[e];
    }
    #pragma unroll
    for (int o = 16; o; o >>= 1) acc += __shfl_xor_sync(0xFFFFFFFFu, acc, o);
    if (lane == 0) g_c[d] = acc;
}

// ============================================================================
// fp16 GEMM: C[m][n] = sum_k A[m][k]*B[n][k], K=768.
// BM=BN=128, BK=64. 128 threads, 4 warps (2m x 2n), 64x64 warp tiles,
// 3-stage cp.async, 96 KB smem, 2 CTAs/SM.
// ============================================================================
__global__ void __launch_bounds__(128, 2)
hgemm_kernel(const __half* __restrict__ A, const __half* __restrict__ B,
             __half* __restrict__ C, int ldc) {
    extern __shared__ char smem[];
    const uint32_t sbase = smem_to_u32(smem);
    const int tid    = threadIdx.x;
    const int wid    = tid >> 5;
    const int lane   = tid & 31;
    const int warp_m = wid >> 1;  // 0..1, 64 rows each
    const int warp_n = wid & 1;   // 0..1, 64 cols each
    const int m0 = blockIdx.y * BM;
    const int n0 = blockIdx.x * BN;

    const __half* Ag = A + (long)m0 * KPA;
    const __half* Bg = B + (long)n0 * KPB;

    auto load_stage = [&](int kt, int st) {
        const int k0 = kt * BK;
        const uint32_t aT = sbase + st * STAGE_BYTES;
        const uint32_t bT = aT + 16384;
        #pragma unroll
        for (int i = 0; i < 8; i++) {
            int idx = tid + i * 128;
            int row = idx >> 3, c = idx & 7;
            cp_async16(aT + SWZ((uint32_t)(row * 128 + c * 16)),
                       (const char*)(Ag + (long)row * KPA + k0) + c * 16);
        }
        #pragma unroll
        for (int i = 0; i < 8; i++) {
            int idx = tid + i * 128;
            int row = idx >> 3, c = idx & 7;
            cp_async16(bT + SWZ((uint32_t)(row * 128 + c * 16)),
                       (const char*)(Bg + (long)row * KPB + k0) + c * 16);
        }
        CP_ASYNC_COMMIT();
    };

    float acc[4][8][4];
    #pragma unroll
    for (int mm = 0; mm < 4; mm++)
        #pragma unroll
        for (int nt = 0; nt < 8; nt++)
            #pragma unroll
            for (int q = 0; q < 4; q++) acc[mm][nt][q] = 0.0f;

    load_stage(0, 0);
    load_stage(1, 1);

    const int rA  = warp_m * 64 + (lane & 7) + ((lane >> 3) & 1) * 8;
    const int kbA = ((lane >> 4) & 1) * 16;
    const int rB  = warp_n * 64 + (lane & 7) + ((lane >> 4) & 1) * 8;
    const int kbB = ((lane >> 3) & 1) * 16;

    for (int kt = 0; kt < KT; kt++) {
        if (kt + 1 < KT) { CP_ASYNC_WAIT(1); } else { CP_ASYNC_WAIT(0); }
        __syncthreads();
        if (kt + 2 < KT) load_stage(kt + 2, (kt + 2) % STAGES);

        const uint32_t aT = sbase + (kt % STAGES) * STAGE_BYTES;
        const uint32_t bT = aT + 16384;

        #pragma unroll
        for (int ks = 0; ks < 4; ks++) {
            uint32_t a[4][4];
            #pragma unroll
            for (int mm = 0; mm < 4; mm++)
                ldsm_x4(a[mm], aT + SWZ((uint32_t)((rA + mm * 16) * 128 +
                                                   ks * 32 + kbA)));
            #pragma unroll
            for (int g = 0; g < 4; g++) {
                uint32_t t[4];
                ldsm_x4(t, bT + SWZ((uint32_t)((rB + g * 16) * 128 +
                                               ks * 32 + kbB)));
                #pragma unroll
                for (int mm = 0; mm < 4; mm++) {
                    mma16816(acc[mm][2 * g],     a[mm], t);
                    mma16816(acc[mm][2 * g + 1], a[mm], t + 2);
                }
            }
        }
        // single barrier per k-tile: stage (kt+2)%3 was last read at kt-1,
        // strictly before this iteration's barrier.
    }

    // Epilogue: fp16 half2 stores
    const int gid = lane >> 2, tig = lane & 3;
    #pragma unroll
    for (int mm = 0; mm < 4; mm++) {
        const long mrow = (long)(m0 + warp_m * 64 + mm * 16 + gid);
        __half* base0 = C + mrow * ldc + n0 + warp_n * 64 + tig * 2;
        __half* base1 = base0 + 8L * ldc;
        #pragma unroll
        for (int nt = 0; nt < 8; nt++) {
            *(__half2*)(base0 + nt * 8) =
                __floats2half2_rn(acc[mm][nt][0], acc[mm][nt][1]);
            *(__half2*)(base1 + nt * 8) =
                __floats2half2_rn(acc[mm][nt][2], acc[mm][nt][3]);
        }
    }
}

// ============================================================================
// Fusion: one warp per token PAIR (r, r+32768), float4/half4 vectorized.
//   P row layout (uint2 = half4 units): m[0:192) | v[192:384); half2 units
//   for the gate: h_a at 768, h_b at 864.
// ============================================================================
__global__ void __launch_bounds__(256) fusion_kernel(
    const float* __restrict__ x1, const float* __restrict__ x2,
    const float* __restrict__ b1, const float* __restrict__ W2,
    const float* __restrict__ b2, float* __restrict__ out) {
    const int t   = blockIdx.x * 8 + (threadIdx.x >> 5);  // pair id 0..32767
    const int lane = threadIdx.x & 31;
    const uint2*   Pr4 = (const uint2*)(g_P + (long)t * NPAD);
    const uint2*   Po4 = (const uint2*)(g_P + (long)(t + HALFM) * NPAD);
    const __half2* Pr2 = (const __half2*)(g_P + (long)t * NPAD);
    const __half2* Po2 = (const __half2*)(g_P + (long)(t + HALFM) * NPAD);
    const float4* xr4 = (const float4*)(x1 + (long)t * DIM);
    const float4* xo4 = (const float4*)(x2 + (long)t * DIM);
    const float4* c4  = (const float4*)g_c;

    float ds_r = 0.0f, dc_r = 0.0f, ds_o = 0.0f, dc_o = 0.0f;
    float4 xrv[6], xov[6];
    #pragma unroll
    for (int i = 0; i < 6; i++) {
        int d4 = lane + i * 32;                 // float4 index 0..191
        uint2 mru = Pr4[d4];
        uint2 mou = Po4[d4];
        float2 mr0 = __half22float2(*(__half2*)&mru.x);
        float2 mr1 = __half22float2(*(__half2*)&mru.y);
        float2 mo0 = __half22float2(*(__half2*)&mou.x);
        float2 mo1 = __half22float2(*(__half2*)&mou.y);
        float4 xs = xr4[d4];
        float4 xq = xo4[d4];
        float4 cc = c4[d4];
        xrv[i] = xs; xov[i] = xq;
        ds_r += (mr0.x + cc.x) * xs.x + (mr0.y + cc.y) * xs.y +
                (mr1.x + cc.z) * xs.z + (mr1.y + cc.w) * xs.w;
        dc_r += mr0.x * xq.x + mr0.y * xq.y + mr1.x * xq.z + mr1.y * xq.w;
        ds_o += (mo0.x + cc.x) * xq.x + (mo0.y + cc.y) * xq.y +
                (mo1.x + cc.z) * xq.z + (mo1.y + cc.w) * xq.w;
        dc_o += mo0.x * xs.x + mo0.y * xs.y + mo1.x * xs.z + mo1.y * xs.w;
    }
    float ha_r = 0.0f, ha_o = 0.0f;
    #pragma unroll
    for (int i = 0; i < 3; i++) {
        int j2 = lane + i * 32;                 // half2 index 0..95
        float2 ar = __half22float2(Pr2[768 + j2]);   // h_a(r)
        float2 br = __half22float2(Pr2[864 + j2]);   // h_b(r)
        float2 ao = __half22float2(Po2[768 + j2]);   // h_a(o)
        float2 bo = __half22float2(Po2[864 + j2]);   // h_b(o)
        float2 bb = *(const float2*)(b1 + 2 * j2);
        float2 ww = *(const float2*)(W2 + 2 * j2);
        float r0 = ar.x + bo.x + bb.x, r1 = ar.y + bo.y + bb.y;
        float o0 = ao.x + br.x + bb.x, o1 = ao.y + br.y + bb.y;
        r0 = 0.5f * r0 * (1.0f + erff(r0 * 0.7071067811865476f));
        r1 = 0.5f * r1 * (1.0f + erff(r1 * 0.7071067811865476f));
        o0 = 0.5f * o0 * (1.0f + erff(o0 * 0.7071067811865476f));
        o1 = 0.5f * o1 * (1.0f + erff(o1 * 0.7071067811865476f));
        ha_r += r0 * ww.x + r1 * ww.y;
        ha_o += o0 * ww.x + o1 * ww.y;
    }
    #pragma unroll
    for (int o = 16; o; o >>= 1) {
        ds_r += __shfl_xor_sync(0xFFFFFFFFu, ds_r, o);
        dc_r += __shfl_xor_sync(0xFFFFFFFFu, dc_r, o);
        ds_o += __shfl_xor_sync(0xFFFFFFFFu, ds_o, o);
        dc_o += __shfl_xor_sync(0xFFFFFFFFu, dc_o, o);
        ha_r += __shfl_xor_sync(0xFFFFFFFFu, ha_r, o);
        ha_o += __shfl_xor_sync(0xFFFFFFFFu, ha_o, o);
    }
    const float bias = b2[0];
    const float SCALE = 0.03608439182435161f;  // 768^-0.5
    float rel_r = 1.0f / (1.0f + expf(-(ha_r + bias)));
    float rel_o = 1.0f / (1.0f + expf(-(ha_o + bias)));
    float d0r = ds_r * SCALE, d1r = dc_r * rel_r * SCALE;
    float d0o = ds_o * SCALE, d1o = dc_o * rel_o * SCALE;
    float mr = fmaxf(d0r, d1r), mo = fmaxf(d0o, d1o);
    float e0r = expf(d0r - mr), e1r = expf(d1r - mr);
    float e0o = expf(d0o - mo), e1o = expf(d1o - mo);
    float ir = 1.0f / (e0r + e1r), io = 1.0f / (e0o + e1o);
    float w0r = e0r * ir, w1r = e1r * ir;
    float w0o = e0o * io, w1o = e1o * io;

    float4* outr = (float4*)(out + (long)t * DIM);
    float4* outo = (float4*)(out + (long)(t + HALFM) * DIM);
    #pragma unroll
    for (int i = 0; i < 6; i++) {
        int d4 = lane + i * 32;
        uint2 vru = Pr4[192 + d4];
        uint2 vou = Po4[192 + d4];
        float2 vr0 = __half22float2(*(__half2*)&vru.x);
        float2 vr1 = __half22float2(*(__half2*)&vru.y);
        float2 vo0 = __half22float2(*(__half2*)&vou.x);
        float2 vo1 = __half22float2(*(__half2*)&vou.y);
        float4 a, b;
        a.x = xrv[i].x + w0r * vr0.x + w1r * vo0.x;
        a.y = xrv[i].y + w0r * vr0.y + w1r * vo0.y;
        a.z = xrv[i].z + w0r * vr1.x + w1r * vo1.x;
        a.w = xrv[i].w + w0r * vr1.y + w1r * vo1.y;
        b.x = xov[i].x + w0o * vo0.x + w1o * vr0.x;
        b.y = xov[i].y + w0o * vo0.y + w1o * vr0.y;
        b.z = xov[i].z + w0o * vo1.x + w1o * vr1.x;
        b.w = xov[i].w + w0o * vo1.y + w1o * vr1.y;
        outr[d4] = a;
        outo[d4] = b;
    }
}

// ============================================================================
// Launch — main gemm is launch #4 (ncu profiles the 4th launch)
// ============================================================================
extern "C" void kernel_launch(void* const* d_in, const int* in_sizes, int n_in,
                              void* d_out, int out_size) {
    const float* x1    = (const float*)d_in[0];
    const float* x2    = (const float*)d_in[1];
    const float* Wq    = (const float*)d_in[2];
    const float* Wk    = (const float*)d_in[3];
    const float* Wv    = (const float*)d_in[4];
    const float* noise = (const float*)d_in[5];
    const float* W1    = (const float*)d_in[6];
    const float* b1    = (const float*)d_in[7];
    const float* W2    = (const float*)d_in[8];
    const float* b2    = (const float*)d_in[9];
    float* out = (float*)d_out;

    cudaFuncSetAttribute(hgemm_kernel,
                         cudaFuncAttributeMaxDynamicSharedMemorySize, SM_TOTAL);

    __half *pXc, *pWc, *pP, *pWq16, *pWk16;
    cudaGetSymbolAddress((void**)&pXc,   g_Xc);
    cudaGetSymbolAddress((void**)&pWc,   g_Wc);
    cudaGetSymbolAddress((void**)&pP,    g_P);
    cudaGetSymbolAddress((void**)&pWq16, g_Wq16);
    cudaGetSymbolAddress((void**)&pWk16, g_Wk16);

    // 1: zero nk (consumed by nk_partial, which runs later, pre-fusion)
    zero_nk_kernel<<<1, 768>>>();
    // 2: all fp16 conversions (qk | w-tail | x)
    prep_all_kernel<<<1920 + XBLK, 256>>>(Wq, Wk, Wv, W1,
                                          (const float4*)x1, (const float4*)x2);
    // 3: M-GEMM: g_Wc[j][i] = sum_e Wk[j,e] * Wq[i,e]  (rows 0..767)
    {
        dim3 grid(DIM / BN, DIM / BM);  // (6, 6)
        hgemm_kernel<<<grid, 128, SM_TOTAL>>>(pWk16, pWq16, pWc, KPB);
    }
    // 4: MAIN GEMM (profiled): P = X @ [M | Wv | W1a | W1b]
    {
        dim3 grid(NPAD / BN, MTOT / BM);  // (15, 512)
        hgemm_kernel<<<grid, 128, SM_TOTAL>>>(pXc, pWc, pP, NPAD);
    }
    // 5,6: nk -> c (only fusion consumes them)
    nk_partial_kernel<<<dim3(6, 16), 128>>>(noise, Wk);
    c_kernel<<<96, 256>>>(Wq);
    // 7: fusion
    fusion_kernel<<<HALFM / 8, 256>>>(x1, x2, b1, W2, b2, out);
}

// round 15
// speedup vs baseline: 3.2300x; 1.0148x over previous
#include <cuda_runtime.h>
#include <cuda_fp16.h>
#include <cstdint>
#include <math.h>

// ============================================================================
//   M = Wq @ Wk^T (768x768).   c = Wq @ (noise@Wk).
//   P = X @ [M | Wv | W1a | W1b] : [65536, 1920]  (m | v | h_a | h_b)
//   d_self = (m + c).x ;  d_cross = m.x_other
// ============================================================================
#define MTOT   65536
#define HALFM  32768
#define DIM    768
#define NPAD   1920
#define KPA    768
#define KPB    768
#define KEFF   768

#define BM 128
#define BN 128
#define BK 64
#define KT (KEFF / BK)         // 12
#define STAGES 3
#define STAGE_BYTES 32768      // A 16KB + B 16KB
#define SM_TOTAL (STAGES * STAGE_BYTES)   // 96 KB -> 2 CTAs/SM

// ============================================================================
// Scratch
// ============================================================================
__device__ __half g_Xc  [(long)MTOT * KPA];
__device__ __half g_Wc  [(long)NPAD * KPB];
__device__ __half g_P   [(long)MTOT * NPAD];
__device__ __half g_Wq16[(long)DIM * DIM];
__device__ __half g_Wk16[(long)DIM * DIM];
__device__ float  g_nk[DIM];
__device__ float  g_c [DIM];

// ============================================================================
// Helpers
// ============================================================================
__device__ __forceinline__ uint32_t smem_to_u32(const void* smem_ptr) {
    uint32_t addr;
    asm("{ .reg .u64 tmp; cvta.to.shared.u64 tmp, %1; cvt.u32.u64 %0, tmp; }"
        : "=r"(addr) : "l"(smem_ptr));
    return addr;
}

#define SWZ(byte_offset) ((byte_offset) ^ ((((uint32_t)(byte_offset)) >> 3) & 0x70))

__device__ __forceinline__ void cp_async16(uint32_t dst_smem, const void* src) {
    asm volatile("cp.async.cg.shared.global [%0], [%1], 16;"
        :: "r"(dst_smem), "l"(src) : "memory");
}
#define CP_ASYNC_COMMIT()  asm volatile("cp.async.commit_group;" ::: "memory")
#define CP_ASYNC_WAIT(N)   asm volatile("cp.async.wait_group %0;" :: "n"(N) : "memory")

__device__ __forceinline__ void ldsm_x4(uint32_t* r, uint32_t addr) {
    asm volatile("ldmatrix.sync.aligned.m8n8.x4.shared.b16 {%0,%1,%2,%3}, [%4];"
        : "=r"(r[0]), "=r"(r[1]), "=r"(r[2]), "=r"(r[3]) : "r"(addr));
}

__device__ __forceinline__ void mma16816(float* c, const uint32_t* a, const uint32_t* b) {
    asm volatile(
        "mma.sync.aligned.m16n8k16.row.col.f32.f16.f16.f32 "
        "{%0,%1,%2,%3}, {%4,%5,%6,%7}, {%8,%9}, {%0,%1,%2,%3};"
        : "+f"(c[0]), "+f"(c[1]), "+f"(c[2]), "+f"(c[3])
        : "r"(a[0]), "r"(a[1]), "r"(a[2]), "r"(a[3]), "r"(b[0]), "r"(b[1]));
}

// ============================================================================
// Prep kernels
// ============================================================================
#define N4H   ((long)HALFM * DIM / 4)        // float4 count per input (6291456)
#define XBLK4 ((unsigned)(2 * N4H / 1024))   // 12288 blocks, 4 float4/thread

// One kernel: [0,768) qk rows | [768,1920) w rows | [1920,..) x chunks (MLP=4)
__global__ void prep_all_kernel(const float*  __restrict__ Wq,
                                const float*  __restrict__ Wk,
                                const float*  __restrict__ Wv,
                                const float*  __restrict__ W1,
                                const float4* __restrict__ x1,
                                const float4* __restrict__ x2) {
    const int b = blockIdx.x;
    if (b < 768) {
        long i = b;
        for (int e = threadIdx.x; e < DIM; e += blockDim.x) {
            g_Wq16[i * DIM + e] = __float2half(Wq[i * DIM + e]);
            g_Wk16[i * DIM + e] = __float2half(Wk[i * DIM + e]);
        }
    } else if (b < 1920) {
        int n = b;  // 768..1919
        __half* dst = g_Wc + (long)n * KPB;
        for (int j = threadIdx.x; j < DIM; j += blockDim.x) {
            float w;
            if      (n < 1536) w = Wv[j * 768 + (n - 768)];
            else if (n < 1728) w = W1[j * 192 + (n - 1536)];
            else               w = W1[(768 + j) * 192 + (n - 1728)];
            dst[j] = __float2half(w);
        }
    } else {
        // 4 independent float4 conversions per thread (MLP=4)
        const long base = (long)(b - 1920) * 1024 + threadIdx.x;
        float4 v[4];
        #pragma unroll
        for (int u = 0; u < 4; u++) {
            long i = base + u * 256;
            v[u] = (i < N4H) ? x1[i] : x2[i - N4H];
        }
        #pragma unroll
        for (int u = 0; u < 4; u++) {
            long i = base + u * 256;
            __half2 lo = __floats2half2_rn(v[u].x, v[u].y);
            __half2 hi = __floats2half2_rn(v[u].z, v[u].w);
            uint2 pack;
            pack.x = *(uint32_t*)&lo;
            pack.y = *(uint32_t*)&hi;
            ((uint2*)g_Xc)[i] = pack;
        }
    }
}

__global__ void zero_nk_kernel() {
    if (threadIdx.x < DIM) g_nk[threadIdx.x] = 0.0f;
}

__global__ void nk_partial_kernel(const float* __restrict__ noise,
                                  const float* __restrict__ Wk) {
    const int d  = blockIdx.x * 128 + threadIdx.x;
    const int j0 = blockIdx.y * 48;
    float acc = 0.0f;
    #pragma unroll
    for (int j = 0; j < 48; j++)
        acc += noise[j0 + j] * Wk[(long)(j0 + j) * 768 + d];
    atomicAdd(&g_nk[d], acc);
}

__global__ void c_kernel(const float* __restrict__ Wq) {
    const int wid  = threadIdx.x >> 5;
    const int lane = threadIdx.x & 31;
    const int d    = blockIdx.x * 8 + wid;
    float acc = 0.0f;
    #pragma unroll
    for (int i = 0; i < 24; i++) {
        int e = lane + i * 32;
        acc += Wq[(long)d * 768 + e] * g_nk[e];
    }
    #pragma unroll
    for (int o = 16; o; o >>= 1) acc += __shfl_xor_sync(0xFFFFFFFFu, acc, o);
    if (lane == 0) g_c[d] = acc;
}

// ============================================================================
// fp16 GEMM: C[m][n] = sum_k A[m][k]*B[n][k], K=768.
// BM=BN=128, BK=64. 128 threads, 4 warps (2m x 2n), 64x64 warp tiles,
// 3-stage cp.async, 96 KB smem, 2 CTAs/SM.  (register-ceiling config)
// ============================================================================
__global__ void __launch_bounds__(128, 2)
hgemm_kernel(const __half* __restrict__ A, const __half* __restrict__ B,
             __half* __restrict__ C, int ldc) {
    extern __shared__ char smem[];
    const uint32_t sbase = smem_to_u32(smem);
    const int tid    = threadIdx.x;
    const int wid    = tid >> 5;
    const int lane   = tid & 31;
    const int warp_m = wid >> 1;  // 0..1, 64 rows each
    const int warp_n = wid & 1;   // 0..1, 64 cols each
    const int m0 = blockIdx.y * BM;
    const int n0 = blockIdx.x * BN;

    const __half* Ag = A + (long)m0 * KPA;
    const __half* Bg = B + (long)n0 * KPB;

    auto load_stage = [&](int kt, int st) {
        const int k0 = kt * BK;
        const uint32_t aT = sbase + st * STAGE_BYTES;
        const uint32_t bT = aT + 16384;
        #pragma unroll
        for (int i = 0; i < 8; i++) {
            int idx = tid + i * 128;
            int row = idx >> 3, c = idx & 7;
            cp_async16(aT + SWZ((uint32_t)(row * 128 + c * 16)),
                       (const char*)(Ag + (long)row * KPA + k0) + c * 16);
        }
        #pragma unroll
        for (int i = 0; i < 8; i++) {
            int idx = tid + i * 128;
            int row = idx >> 3, c = idx & 7;
            cp_async16(bT + SWZ((uint32_t)(row * 128 + c * 16)),
                       (const char*)(Bg + (long)row * KPB + k0) + c * 16);
        }
        CP_ASYNC_COMMIT();
    };

    float acc[4][8][4];
    #pragma unroll
    for (int mm = 0; mm < 4; mm++)
        #pragma unroll
        for (int nt = 0; nt < 8; nt++)
            #pragma unroll
            for (int q = 0; q < 4; q++) acc[mm][nt][q] = 0.0f;

    load_stage(0, 0);
    load_stage(1, 1);

    const int rA  = warp_m * 64 + (lane & 7) + ((lane >> 3) & 1) * 8;
    const int kbA = ((lane >> 4) & 1) * 16;
    const int rB  = warp_n * 64 + (lane & 7) + ((lane >> 4) & 1) * 8;
    const int kbB = ((lane >> 3) & 1) * 16;

    for (int kt = 0; kt < KT; kt++) {
        if (kt + 1 < KT) { CP_ASYNC_WAIT(1); } else { CP_ASYNC_WAIT(0); }
        __syncthreads();
        if (kt + 2 < KT) load_stage(kt + 2, (kt + 2) % STAGES);

        const uint32_t aT = sbase + (kt % STAGES) * STAGE_BYTES;
        const uint32_t bT = aT + 16384;

        #pragma unroll
        for (int ks = 0; ks < 4; ks++) {
            uint32_t a[4][4];
            #pragma unroll
            for (int mm = 0; mm < 4; mm++)
                ldsm_x4(a[mm], aT + SWZ((uint32_t)((rA + mm * 16) * 128 +
                                                   ks * 32 + kbA)));
            #pragma unroll
            for (int g = 0; g < 4; g++) {
                uint32_t t[4];
                ldsm_x4(t, bT + SWZ((uint32_t)((rB + g * 16) * 128 +
                                               ks * 32 + kbB)));
                #pragma unroll
                for (int mm = 0; mm < 4; mm++) {
                    mma16816(acc[mm][2 * g],     a[mm], t);
                    mma16816(acc[mm][2 * g + 1], a[mm], t + 2);
                }
            }
        }
        // single barrier per k-tile: stage (kt+2)%3 was last read at kt-1,
        // strictly before this iteration's barrier.
    }

    // Epilogue: fp16 half2 stores
    const int gid = lane >> 2, tig = lane & 3;
    #pragma unroll
    for (int mm = 0; mm < 4; mm++) {
        const long mrow = (long)(m0 + warp_m * 64 + mm * 16 + gid);
        __half* base0 = C + mrow * ldc + n0 + warp_n * 64 + tig * 2;
        __half* base1 = base0 + 8L * ldc;
        #pragma unroll
        for (int nt = 0; nt < 8; nt++) {
            *(__half2*)(base0 + nt * 8) =
                __floats2half2_rn(acc[mm][nt][0], acc[mm][nt][1]);
            *(__half2*)(base1 + nt * 8) =
                __floats2half2_rn(acc[mm][nt][2], acc[mm][nt][3]);
        }
    }
}

// ============================================================================
// Fusion: one warp per token PAIR (r, r+32768), float4/half4 vectorized.
// x re-read in the output loop (L1/L2-warm) instead of register-cached:
// fewer regs -> higher occupancy / more loads in flight.
// ============================================================================
__global__ void __launch_bounds__(256) fusion_kernel(
    const float* __restrict__ x1, const float* __restrict__ x2,
    const float* __restrict__ b1, const float* __restrict__ W2,
    const float* __restrict__ b2, float* __restrict__ out) {
    const int t   = blockIdx.x * 8 + (threadIdx.x >> 5);  // pair id 0..32767
    const int lane = threadIdx.x & 31;
    const uint2*   Pr4 = (const uint2*)(g_P + (long)t * NPAD);
    const uint2*   Po4 = (const uint2*)(g_P + (long)(t + HALFM) * NPAD);
    const __half2* Pr2 = (const __half2*)(g_P + (long)t * NPAD);
    const __half2* Po2 = (const __half2*)(g_P + (long)(t + HALFM) * NPAD);
    const float4* xr4 = (const float4*)(x1 + (long)t * DIM);
    const float4* xo4 = (const float4*)(x2 + (long)t * DIM);
    const float4* c4  = (const float4*)g_c;

    float ds_r = 0.0f, dc_r = 0.0f, ds_o = 0.0f, dc_o = 0.0f;
    #pragma unroll
    for (int i = 0; i < 6; i++) {
        int d4 = lane + i * 32;                 // float4 index 0..191
        uint2 mru = Pr4[d4];
        uint2 mou = Po4[d4];
        float2 mr0 = __half22float2(*(__half2*)&mru.x);
        float2 mr1 = __half22float2(*(__half2*)&mru.y);
        float2 mo0 = __half22float2(*(__half2*)&mou.x);
        float2 mo1 = __half22float2(*(__half2*)&mou.y);
        float4 xs = xr4[d4];
        float4 xq = xo4[d4];
        float4 cc = c4[d4];
        ds_r += (mr0.x + cc.x) * xs.x + (mr0.y + cc.y) * xs.y +
                (mr1.x + cc.z) * xs.z + (mr1.y + cc.w) * xs.w;
        dc_r += mr0.x * xq.x + mr0.y * xq.y + mr1.x * xq.z + mr1.y * xq.w;
        ds_o += (mo0.x + cc.x) * xq.x + (mo0.y + cc.y) * xq.y +
                (mo1.x + cc.z) * xq.z + (mo1.y + cc.w) * xq.w;
        dc_o += mo0.x * xs.x + mo0.y * xs.y + mo1.x * xs.z + mo1.y * xs.w;
    }
    float ha_r = 0.0f, ha_o = 0.0f;
    #pragma unroll
    for (int i = 0; i < 3; i++) {
        int j2 = lane + i * 32;                 // half2 index 0..95
        float2 ar = __half22float2(Pr2[768 + j2]);   // h_a(r)
        float2 br = __half22float2(Pr2[864 + j2]);   // h_b(r)
        float2 ao = __half22float2(Po2[768 + j2]);   // h_a(o)
        float2 bo = __half22float2(Po2[864 + j2]);   // h_b(o)
        float2 bb = *(const float2*)(b1 + 2 * j2);
        float2 ww = *(const float2*)(W2 + 2 * j2);
        float r0 = ar.x + bo.x + bb.x, r1 = ar.y + bo.y + bb.y;
        float o0 = ao.x + br.x + bb.x, o1 = ao.y + br.y + bb.y;
        r0 = 0.5f * r0 * (1.0f + erff(r0 * 0.7071067811865476f));
        r1 = 0.5f * r1 * (1.0f + erff(r1 * 0.7071067811865476f));
        o0 = 0.5f * o0 * (1.0f + erff(o0 * 0.7071067811865476f));
        o1 = 0.5f * o1 * (1.0f + erff(o1 * 0.7071067811865476f));
        ha_r += r0 * ww.x + r1 * ww.y;
        ha_o += o0 * ww.x + o1 * ww.y;
    }
    #pragma unroll
    for (int o = 16; o; o >>= 1) {
        ds_r += __shfl_xor_sync(0xFFFFFFFFu, ds_r, o);
        dc_r += __shfl_xor_sync(0xFFFFFFFFu, dc_r, o);
        ds_o += __shfl_xor_sync(0xFFFFFFFFu, ds_o, o);
        dc_o += __shfl_xor_sync(0xFFFFFFFFu, dc_o, o);
        ha_r += __shfl_xor_sync(0xFFFFFFFFu, ha_r, o);
        ha_o += __shfl_xor_sync(0xFFFFFFFFu, ha_o, o);
    }
    const float bias = b2[0];
    const float SCALE = 0.03608439182435161f;  // 768^-0.5
    float rel_r = 1.0f / (1.0f + expf(-(ha_r + bias)));
    float rel_o = 1.0f / (1.0f + expf(-(ha_o + bias)));
    float d0r = ds_r * SCALE, d1r = dc_r * rel_r * SCALE;
    float d0o = ds_o * SCALE, d1o = dc_o * rel_o * SCALE;
    float mr = fmaxf(d0r, d1r), mo = fmaxf(d0o, d1o);
    float e0r = expf(d0r - mr), e1r = expf(d1r - mr);
    float e0o = expf(d0o - mo), e1o = expf(d1o - mo);
    float ir = 1.0f / (e0r + e1r), io = 1.0f / (e0o + e1o);
    float w0r = e0r * ir, w1r = e1r * ir;
    float w0o = e0o * io, w1o = e1o * io;

    float4* outr = (float4*)(out + (long)t * DIM);
    float4* outo = (float4*)(out + (long)(t + HALFM) * DIM);
    #pragma unroll
    for (int i = 0; i < 6; i++) {
        int d4 = lane + i * 32;
        uint2 vru = Pr4[192 + d4];
        uint2 vou = Po4[192 + d4];
        float4 xs = xr4[d4];     // L1/L2-warm re-read
        float4 xq = xo4[d4];
        float2 vr0 = __half22float2(*(__half2*)&vru.x);
        float2 vr1 = __half22float2(*(__half2*)&vru.y);
        float2 vo0 = __half22float2(*(__half2*)&vou.x);
        float2 vo1 = __half22float2(*(__half2*)&vou.y);
        float4 a, b;
        a.x = xs.x + w0r * vr0.x + w1r * vo0.x;
        a.y = xs.y + w0r * vr0.y + w1r * vo0.y;
        a.z = xs.z + w0r * vr1.x + w1r * vo1.x;
        a.w = xs.w + w0r * vr1.y + w1r * vo1.y;
        b.x = xq.x + w0o * vo0.x + w1o * vr0.x;
        b.y = xq.y + w0o * vo0.y + w1o * vr0.y;
        b.z = xq.z + w0o * vo1.x + w1o * vr1.x;
        b.w = xq.w + w0o * vo1.y + w1o * vr1.y;
        outr[d4] = a;
        outo[d4] = b;
    }
}

// ============================================================================
// Launch — main gemm is launch #4 (ncu profiles the 4th launch)
// ============================================================================
extern "C" void kernel_launch(void* const* d_in, const int* in_sizes, int n_in,
                              void* d_out, int out_size) {
    const float* x1    = (const float*)d_in[0];
    const float* x2    = (const float*)d_in[1];
    const float* Wq    = (const float*)d_in[2];
    const float* Wk    = (const float*)d_in[3];
    const float* Wv    = (const float*)d_in[4];
    const float* noise = (const float*)d_in[5];
    const float* W1    = (const float*)d_in[6];
    const float* b1    = (const float*)d_in[7];
    const float* W2    = (const float*)d_in[8];
    const float* b2    = (const float*)d_in[9];
    float* out = (float*)d_out;

    cudaFuncSetAttribute(hgemm_kernel,
                         cudaFuncAttributeMaxDynamicSharedMemorySize, SM_TOTAL);

    __half *pXc, *pWc, *pP, *pWq16, *pWk16;
    cudaGetSymbolAddress((void**)&pXc,   g_Xc);
    cudaGetSymbolAddress((void**)&pWc,   g_Wc);
    cudaGetSymbolAddress((void**)&pP,    g_P);
    cudaGetSymbolAddress((void**)&pWq16, g_Wq16);
    cudaGetSymbolAddress((void**)&pWk16, g_Wk16);

    // 1: zero nk
    zero_nk_kernel<<<1, 768>>>();
    // 2: all fp16 conversions (qk | w-tail | x @ MLP=4)
    prep_all_kernel<<<1920 + XBLK4, 256>>>(Wq, Wk, Wv, W1,
                                           (const float4*)x1, (const float4*)x2);
    // 3: M-GEMM: g_Wc[j][i] = sum_e Wk[j,e] * Wq[i,e]  (rows 0..767)
    {
        dim3 grid(DIM / BN, DIM / BM);  // (6, 6)
        hgemm_kernel<<<grid, 128, SM_TOTAL>>>(pWk16, pWq16, pWc, KPB);
    }
    // 4: MAIN GEMM (profiled): P = X @ [M | Wv | W1a | W1b]
    {
        dim3 grid(NPAD / BN, MTOT / BM);  // (15, 512)
        hgemm_kernel<<<grid, 128, SM_TOTAL>>>(pXc, pWc, pP, NPAD);
    }
    // 5,6: nk -> c (only fusion consumes them)
    nk_partial_kernel<<<dim3(6, 16), 128>>>(noise, Wk);
    c_kernel<<<96, 256>>>(Wq);
    // 7: fusion
    fusion_kernel<<<HALFM / 8, 256>>>(x1, x2, b1, W2, b2, out);
}